// round 1
// baseline (speedup 1.0000x reference)
#include <cuda_runtime.h>
#include <cuda_bf16.h>

// Problem constants
#define BATCH 4
#define TSEQ 4096
#define DMODEL 2048
#define NLAT 64
#define DLAT 1024
#define NHEADS 16
#define DHEAD 64
#define BT (BATCH * TSEQ)        // 16384

// ---------------------------------------------------------------------------
// Scratch: one big __device__ global (allocation-free per harness rules).
// Layout (floats):
//   K     : [BT, DLAT]            @ 0
//   V     : [BT, DLAT]            @ 16777216
//   Qx    : [BT, DLAT]            @ 33554432
//   xlat  : [BT, DLAT]            @ 50331648
//   q1    : [NLAT, DLAT]          @ 67108864
//   z     : [B, NLAT, DLAT]       @ 67174400
//   z2    : [B, NLAT, DLAT]       @ 67436544
//   Ql    : [B, NLAT, DLAT]       @ 67698688
//   Kl    : [B, NLAT, DLAT]       @ 67960832
//   Vl    : [B, NLAT, DLAT]       @ 68222976
//   Kz    : [B, NLAT, DLAT]       @ 68485120
//   Vz    : [B, NLAT, DLAT]       @ 68747264
// total 69009408 floats (~276 MB)
// ---------------------------------------------------------------------------
#define OFF_K    0L
#define OFF_V    16777216L
#define OFF_QX   33554432L
#define OFF_XLAT 50331648L
#define OFF_Q1   67108864L
#define OFF_Z    67174400L
#define OFF_Z2   67436544L
#define OFF_QL   67698688L
#define OFF_KL   67960832L
#define OFF_VL   68222976L
#define OFF_KZ   68485120L
#define OFF_VZ   68747264L
#define SCRATCH_FLOATS 69009408L

__device__ float g_scratch[SCRATCH_FLOATS];

// ---------------------------------------------------------------------------
// SGEMM: C[M,N] = A[M,K] * B[K,N], row-major fp32.
// 128x128 tile, BK=8, 256 threads, 8x8 per-thread register tile.
// Requires: N % 128 == 0, K % 8 == 0. M arbitrary (guarded).
// ---------------------------------------------------------------------------
#define BM 128
#define BN 128
#define BKK 8
#define LDA 132   // padded row stride for As (conflict-free transposed stores)

__global__ __launch_bounds__(256) void sgemm128(
    const float* __restrict__ A, const float* __restrict__ B,
    float* __restrict__ C, int M, int N, int K)
{
    __shared__ float As[BKK * LDA];   // As[k][m], padded
    __shared__ float Bs[BKK * LDA];   // Bs[k][n], padded

    int tid = threadIdx.x;
    int bx = blockIdx.x;              // N tile
    int by = blockIdx.y;              // M tile
    int tx = tid & 15;
    int ty = tid >> 4;
    int row0 = by * BM;
    int col0 = bx * BN;

    // A load mapping: thread -> float4 at (arow, acol)
    int arow = tid >> 1;
    int acol = (tid & 1) * 4;
    // B load mapping: thread -> float4 at (brow, bcol)
    int brow = tid >> 5;
    int bcol = (tid & 31) * 4;

    float acc[8][8];
#pragma unroll
    for (int i = 0; i < 8; i++)
#pragma unroll
        for (int j = 0; j < 8; j++) acc[i][j] = 0.0f;

    for (int k0 = 0; k0 < K; k0 += BKK) {
        float4 a4 = make_float4(0.f, 0.f, 0.f, 0.f);
        if (row0 + arow < M)
            a4 = *(const float4*)(A + (long)(row0 + arow) * K + k0 + acol);
        As[(acol + 0) * LDA + arow] = a4.x;
        As[(acol + 1) * LDA + arow] = a4.y;
        As[(acol + 2) * LDA + arow] = a4.z;
        As[(acol + 3) * LDA + arow] = a4.w;

        float4 b4 = *(const float4*)(B + (long)(k0 + brow) * N + col0 + bcol);
        *(float4*)&Bs[brow * LDA + bcol] = b4;
        __syncthreads();

#pragma unroll
        for (int kk = 0; kk < BKK; kk++) {
            float af[8], bf[8];
            *(float4*)&af[0] = *(float4*)&As[kk * LDA + ty * 8];
            *(float4*)&af[4] = *(float4*)&As[kk * LDA + ty * 8 + 4];
            *(float4*)&bf[0] = *(float4*)&Bs[kk * LDA + tx * 8];
            *(float4*)&bf[4] = *(float4*)&Bs[kk * LDA + tx * 8 + 4];
#pragma unroll
            for (int i = 0; i < 8; i++)
#pragma unroll
                for (int j = 0; j < 8; j++)
                    acc[i][j] += af[i] * bf[j];
        }
        __syncthreads();
    }

#pragma unroll
    for (int i = 0; i < 8; i++) {
        int r = row0 + ty * 8 + i;
        if (r < M) {
            float* cp = C + (long)r * N + col0 + tx * 8;
            *(float4*)cp = make_float4(acc[i][0], acc[i][1], acc[i][2], acc[i][3]);
            *(float4*)(cp + 4) = make_float4(acc[i][4], acc[i][5], acc[i][6], acc[i][7]);
        }
    }
}

// ---------------------------------------------------------------------------
// Unified flash attention for d_h = 64, head-packed layout [*, row, h*64+d].
// Each block: one 64-query tile of one (b, h); loops over 64-key chunks with
// online softmax; O fragments live in registers (4x4 per thread).
//   Q rows at: Q + b*qBatch + (qtile*64+q)*1024 + h*64
//   K/V rows:  Kp/Vp + b*kvBatch + k*1024 + h*64
//   Out rows:  Out + b*oBatch + (qtile*64+q)*1024 + h*64
// grid = (numQTiles, NHEADS, BATCH), 256 threads.
// dynamic smem: 4 * 64*68 + 192 floats = 70400 B
// ---------------------------------------------------------------------------
#define ALD 68

__global__ __launch_bounds__(256) void attn64(
    const float* __restrict__ Q, long qBatch,
    const float* __restrict__ Kp, const float* __restrict__ Vp, long kvBatch,
    int nkeys, float* __restrict__ Out, long oBatch)
{
    extern __shared__ float sm[];
    float* Qs = sm;                   // [d][q]  d-major, scaled
    float* Ks = Qs + 64 * ALD;        // [d][k]  d-major
    float* Vs = Ks + 64 * ALD;        // [j][d]  row-major
    float* Ps = Vs + 64 * ALD;        // [k][q]  scores / probabilities
    float* mrow = Ps + 64 * ALD;      // [64]
    float* lrow = mrow + 64;          // [64]
    float* crow = lrow + 64;          // [64]

    int tid = threadIdx.x;
    int h = blockIdx.y, b = blockIdx.z;
    int qtile = blockIdx.x;
    const float scale = 0.125f;       // 1/sqrt(64)

    const float* Qbase = Q + (long)b * qBatch + (long)qtile * 64 * DLAT + h * DHEAD;
    const float* Kbase = Kp + (long)b * kvBatch + h * DHEAD;
    const float* Vbase = Vp + (long)b * kvBatch + h * DHEAD;

    // Load Q tile (transposed to d-major), pre-scaled
#pragma unroll
    for (int i = 0; i < 16; i++) {
        int idx = tid + 256 * i;       // 0..4095
        int q = idx >> 6, d = idx & 63;
        Qs[d * ALD + q] = Qbase[(long)q * DLAT + d] * scale;
    }
    if (tid < 64) { mrow[tid] = -1e30f; lrow[tid] = 0.0f; }
    __syncthreads();

    int tx = tid & 15, ty = tid >> 4;  // tx -> key/dim frag, ty -> query frag
    float o[4][4];
#pragma unroll
    for (int i = 0; i < 4; i++)
#pragma unroll
        for (int j = 0; j < 4; j++) o[i][j] = 0.0f;

    for (int k0 = 0; k0 < nkeys; k0 += 64) {
        // Load K (transposed) and V (direct) chunk
#pragma unroll
        for (int i = 0; i < 16; i++) {
            int idx = tid + 256 * i;
            int k = idx >> 6, d = idx & 63;
            float kv = Kbase[(long)(k0 + k) * DLAT + d];
            float vv = Vbase[(long)(k0 + k) * DLAT + d];
            Ks[d * ALD + k] = kv;
            Vs[k * ALD + d] = vv;
        }
        __syncthreads();

        // S = (scaled Q) . K : s[ki][qj], k = tx*4+ki, q = ty*4+qj
        float s[4][4];
#pragma unroll
        for (int i = 0; i < 4; i++)
#pragma unroll
            for (int j = 0; j < 4; j++) s[i][j] = 0.0f;
#pragma unroll
        for (int d = 0; d < 64; d++) {
            float4 qf = *(float4*)&Qs[d * ALD + ty * 4];
            float4 kf = *(float4*)&Ks[d * ALD + tx * 4];
            float qa[4] = {qf.x, qf.y, qf.z, qf.w};
            float ka[4] = {kf.x, kf.y, kf.z, kf.w};
#pragma unroll
            for (int ki = 0; ki < 4; ki++)
#pragma unroll
                for (int qj = 0; qj < 4; qj++)
                    s[ki][qj] += ka[ki] * qa[qj];
        }
#pragma unroll
        for (int ki = 0; ki < 4; ki++)
            *(float4*)&Ps[(tx * 4 + ki) * ALD + ty * 4] =
                make_float4(s[ki][0], s[ki][1], s[ki][2], s[ki][3]);
        __syncthreads();

        // Online softmax update (one thread per query row)
        if (tid < 64) {
            int q = tid;
            float mold = mrow[q];
            float mx = mold;
            for (int k = 0; k < 64; k++) mx = fmaxf(mx, Ps[k * ALD + q]);
            float c = __expf(mold - mx);
            float l = lrow[q] * c;
            for (int k = 0; k < 64; k++) {
                float p = __expf(Ps[k * ALD + q] - mx);
                Ps[k * ALD + q] = p;
                l += p;
            }
            mrow[q] = mx; lrow[q] = l; crow[q] = c;
        }
        __syncthreads();

        // Rescale O fragments and accumulate P @ V
        float cq[4];
        *(float4*)cq = *(float4*)&crow[ty * 4];
#pragma unroll
        for (int i = 0; i < 4; i++)
#pragma unroll
            for (int j = 0; j < 4; j++) o[i][j] *= cq[i];

#pragma unroll 8
        for (int j = 0; j < 64; j++) {
            float4 pf = *(float4*)&Ps[j * ALD + ty * 4];
            float4 vf = *(float4*)&Vs[j * ALD + tx * 4];
            float pa[4] = {pf.x, pf.y, pf.z, pf.w};
            float va[4] = {vf.x, vf.y, vf.z, vf.w};
#pragma unroll
            for (int qi = 0; qi < 4; qi++)
#pragma unroll
                for (int dj = 0; dj < 4; dj++)
                    o[qi][dj] += pa[qi] * va[dj];
        }
        __syncthreads();
    }

    // Epilogue: normalize by l, store
    float lq[4];
    *(float4*)lq = *(float4*)&lrow[ty * 4];
    float* Obase = Out + (long)b * oBatch + (long)qtile * 64 * DLAT + h * DHEAD;
#pragma unroll
    for (int qi = 0; qi < 4; qi++) {
        float inv = 1.0f / lq[qi];
        int q = ty * 4 + qi;
        float* op = Obase + (long)q * DLAT + tx * 4;
        *(float4*)op = make_float4(o[qi][0] * inv, o[qi][1] * inv,
                                   o[qi][2] * inv, o[qi][3] * inv);
    }
}

// ---------------------------------------------------------------------------
// Host launch
// ---------------------------------------------------------------------------
static void launch_gemm(const float* A, const float* B, float* C,
                        int M, int N, int K)
{
    dim3 grid(N / BN, (M + BM - 1) / BM);
    sgemm128<<<grid, 256>>>(A, B, C, M, N, K);
}

extern "C" void kernel_launch(void* const* d_in, const int* in_sizes, int n_in,
                              void* d_out, int out_size)
{
    const float* x       = (const float*)d_in[0];
    const float* L       = (const float*)d_in[1];
    const float* W_q_lat = (const float*)d_in[2];
    const float* W_k_in  = (const float*)d_in[3];
    const float* W_v_in  = (const float*)d_in[4];
    const float* W_q_in  = (const float*)d_in[5];
    const float* W_k_lat = (const float*)d_in[6];
    const float* W_v_lat = (const float*)d_in[7];
    const float* W_out   = (const float*)d_in[8];
    float* out = (float*)d_out;

    float* scratch = nullptr;
    cudaGetSymbolAddress((void**)&scratch, g_scratch);

    float* gK    = scratch + OFF_K;
    float* gV    = scratch + OFF_V;
    float* gQx   = scratch + OFF_QX;
    float* gXlat = scratch + OFF_XLAT;
    float* gQ1   = scratch + OFF_Q1;
    float* gZ    = scratch + OFF_Z;
    float* gZ2   = scratch + OFF_Z2;
    float* gQl   = scratch + OFF_QL;
    float* gKl   = scratch + OFF_KL;
    float* gVl   = scratch + OFF_VL;
    float* gKz   = scratch + OFF_KZ;
    float* gVz   = scratch + OFF_VZ;

    const int ATTN_SMEM = (4 * 64 * ALD + 192) * 4;   // 70400 B
    cudaFuncSetAttribute(attn64, cudaFuncAttributeMaxDynamicSharedMemorySize,
                         ATTN_SMEM);

    // --- Stage 0: big input projections ---
    launch_gemm(x, W_k_in, gK, BT, DLAT, DMODEL);     // K  [BT, DLAT]
    launch_gemm(x, W_v_in, gV, BT, DLAT, DMODEL);     // V  [BT, DLAT]
    launch_gemm(x, W_q_in, gQx, BT, DLAT, DMODEL);    // Qx [BT, DLAT]
    launch_gemm(L, W_q_lat, gQ1, NLAT, DLAT, DLAT);   // q1 [NLAT, DLAT]

    // --- Stage 1: latents attend to tokens ---
    {
        dim3 grid(1, NHEADS, BATCH);
        attn64<<<grid, 256, ATTN_SMEM>>>(gQ1, 0L, gK, gV,
                                         (long)TSEQ * DLAT, TSEQ,
                                         gZ, (long)NLAT * DLAT);
    }

    // --- Stage 2 projections (z flattened to [B*NLAT, DLAT]) ---
    launch_gemm(gZ, W_q_lat, gQl, BATCH * NLAT, DLAT, DLAT);
    launch_gemm(gZ, W_k_lat, gKl, BATCH * NLAT, DLAT, DLAT);
    launch_gemm(gZ, W_v_lat, gVl, BATCH * NLAT, DLAT, DLAT);

    // --- Stage 2: latent self-attention ---
    {
        dim3 grid(1, NHEADS, BATCH);
        attn64<<<grid, 256, ATTN_SMEM>>>(gQl, (long)NLAT * DLAT, gKl, gVl,
                                         (long)NLAT * DLAT, NLAT,
                                         gZ2, (long)NLAT * DLAT);
    }

    // --- Stage 3 projections ---
    launch_gemm(gZ2, W_k_lat, gKz, BATCH * NLAT, DLAT, DLAT);
    launch_gemm(gZ2, W_v_lat, gVz, BATCH * NLAT, DLAT, DLAT);

    // --- Stage 3: tokens attend to latents ---
    {
        dim3 grid(TSEQ / 64, NHEADS, BATCH);
        attn64<<<grid, 256, ATTN_SMEM>>>(gQx, (long)TSEQ * DLAT, gKz, gVz,
                                         (long)NLAT * DLAT, NLAT,
                                         gXlat, (long)TSEQ * DLAT);
    }

    // --- Output projection ---
    launch_gemm(gXlat, W_out, out, BT, DMODEL, DLAT);
}

// round 4
// speedup vs baseline: 2.6099x; 2.6099x over previous
#include <cuda_runtime.h>
#include <cuda_bf16.h>
#include <cstdint>

// Problem constants
#define BATCH 4
#define TSEQ 4096
#define DMODEL 2048
#define NLAT 64
#define DLAT 1024
#define NHEADS 16
#define DHEAD 64
#define BT (BATCH * TSEQ)        // 16384

// ---------------------------------------------------------------------------
// Scratch offsets (floats)
// ---------------------------------------------------------------------------
#define OFF_K      0L
#define OFF_V      16777216L
#define OFF_QX     33554432L
#define OFF_XLAT   50331648L
#define OFF_Q1     67108864L
#define OFF_Z      67174400L
#define OFF_Z2     67436544L
#define OFF_QL     67698688L
#define OFF_KL     67960832L
#define OFF_VL     68222976L
#define OFF_KZ     68485120L
#define OFF_VZ     68747264L
// transposed weights [N,K]
#define OFF_WKINT  69009408L
#define OFF_WVINT  71106560L
#define OFF_WQINT  73203712L
#define OFF_WQLATT 75300864L
#define OFF_WKLATT 76349440L
#define OFF_WVLATT 77398016L
#define OFF_WOUTT  78446592L
#define SCRATCH_FLOATS 80543744L

__device__ float g_scratch[SCRATCH_FLOATS];

__device__ __forceinline__ uint32_t tf32r(float x) {
    uint32_t r;
    asm("cvt.rna.tf32.f32 %0, %1;" : "=r"(r) : "f"(x));
    return r;
}

// ---------------------------------------------------------------------------
// tf32 mma.sync GEMM: C[M,N] = A[M,K] * Bt[N,K]^T (Bt is [N,K] K-major).
// CTA tile 128x128, BK=16, 256 threads (8 warps, 4x2), warp tile 32x64.
// Each warp: 2 M-frags x 8 N-frags of m16n8k8. Double-buffered SMEM,
// register prefetch of the next chunk. Requires N%128==0, K%16==0.
// ---------------------------------------------------------------------------
#define GBM 128
#define GBN 128
#define GBK 16
#define LDSA 20                       // padded floats per row (16+4)
#define BUF_FLOATS (GBM * LDSA)       // 2560 per array
#define GEMM_SMEM (2 * 2 * BUF_FLOATS * 4)   // 40960 bytes

__global__ __launch_bounds__(256, 2) void gemm_mma(
    const float* __restrict__ A, const float* __restrict__ Bt,
    float* __restrict__ C, int M, int N, int K)
{
    extern __shared__ float sm[];
    const int tid = threadIdx.x;
    const int wid = tid >> 5, lane = tid & 31;
    const int grp = lane >> 2, qc = lane & 3;     // mma fragment coords
    const int warp_m = wid & 3, warp_n = wid >> 2;
    const int row0 = blockIdx.y * GBM;
    const int col0 = blockIdx.x * GBN;
    const int nchunks = K / GBK;

    float acc[2][8][4];
#pragma unroll
    for (int i = 0; i < 2; i++)
#pragma unroll
        for (int j = 0; j < 8; j++)
#pragma unroll
            for (int l = 0; l < 4; l++) acc[i][j][l] = 0.0f;

    // Per-thread global-load mapping: 2 float4 for A, 2 for B per chunk.
    // chunk = 128 rows x 16 floats = 512 float4; f4 = tid + 256*i.
    float4 apre[2], bpre[2];

    const float* Abase = A + (long)row0 * K;
    const float* Bbase = Bt + (long)col0 * K;

    // prefetch chunk 0
#pragma unroll
    for (int i = 0; i < 2; i++) {
        int f4 = tid + 256 * i;
        int r = f4 >> 2, cc = (f4 & 3) * 4;
        apre[i] = (row0 + r < M) ? *(const float4*)(Abase + (long)r * K + cc)
                                 : make_float4(0.f, 0.f, 0.f, 0.f);
        bpre[i] = *(const float4*)(Bbase + (long)r * K + cc);
    }

    for (int c = 0; c < nchunks; c++) {
        float* As = sm + (c & 1) * (2 * BUF_FLOATS);
        float* Bs = As + BUF_FLOATS;

        // store prefetched chunk (tf32-rounded)
#pragma unroll
        for (int i = 0; i < 2; i++) {
            int f4 = tid + 256 * i;
            int r = f4 >> 2, cc = (f4 & 3) * 4;
            uint32_t* pa = (uint32_t*)(As + r * LDSA + cc);
            pa[0] = tf32r(apre[i].x); pa[1] = tf32r(apre[i].y);
            pa[2] = tf32r(apre[i].z); pa[3] = tf32r(apre[i].w);
            uint32_t* pb = (uint32_t*)(Bs + r * LDSA + cc);
            pb[0] = tf32r(bpre[i].x); pb[1] = tf32r(bpre[i].y);
            pb[2] = tf32r(bpre[i].z); pb[3] = tf32r(bpre[i].w);
        }
        __syncthreads();

        // prefetch next chunk
        if (c + 1 < nchunks) {
            const float* An = Abase + (c + 1) * GBK;
            const float* Bn = Bbase + (c + 1) * GBK;
#pragma unroll
            for (int i = 0; i < 2; i++) {
                int f4 = tid + 256 * i;
                int r = f4 >> 2, cc = (f4 & 3) * 4;
                apre[i] = (row0 + r < M) ? *(const float4*)(An + (long)r * K + cc)
                                         : make_float4(0.f, 0.f, 0.f, 0.f);
                bpre[i] = *(const float4*)(Bn + (long)r * K + cc);
            }
        }

        // compute: 2 k-slices of 8
#pragma unroll
        for (int ks = 0; ks < 2; ks++) {
            int k0 = ks * 8;
            uint32_t a[2][4], b[8][2];
#pragma unroll
            for (int mt = 0; mt < 2; mt++) {
                int r = warp_m * 32 + mt * 16 + grp;
                const uint32_t* p0 = (const uint32_t*)(As + r * LDSA + k0 + qc);
                const uint32_t* p1 = (const uint32_t*)(As + (r + 8) * LDSA + k0 + qc);
                a[mt][0] = p0[0]; a[mt][2] = p0[4];
                a[mt][1] = p1[0]; a[mt][3] = p1[4];
            }
#pragma unroll
            for (int nt = 0; nt < 8; nt++) {
                int r = warp_n * 64 + nt * 8 + grp;
                const uint32_t* p = (const uint32_t*)(Bs + r * LDSA + k0 + qc);
                b[nt][0] = p[0]; b[nt][1] = p[4];
            }
#pragma unroll
            for (int mt = 0; mt < 2; mt++)
#pragma unroll
                for (int nt = 0; nt < 8; nt++)
                    asm volatile(
                        "mma.sync.aligned.m16n8k8.row.col.f32.tf32.tf32.f32 "
                        "{%0,%1,%2,%3}, {%4,%5,%6,%7}, {%8,%9}, {%0,%1,%2,%3};"
                        : "+f"(acc[mt][nt][0]), "+f"(acc[mt][nt][1]),
                          "+f"(acc[mt][nt][2]), "+f"(acc[mt][nt][3])
                        : "r"(a[mt][0]), "r"(a[mt][1]), "r"(a[mt][2]), "r"(a[mt][3]),
                          "r"(b[nt][0]), "r"(b[nt][1]));
        }
        __syncthreads();
    }

    // Epilogue
#pragma unroll
    for (int mt = 0; mt < 2; mt++) {
        int r = row0 + warp_m * 32 + mt * 16 + grp;
#pragma unroll
        for (int nt = 0; nt < 8; nt++) {
            int col = col0 + warp_n * 64 + nt * 8 + qc * 2;
            if (r < M)
                *(float2*)(C + (long)r * N + col) =
                    make_float2(acc[mt][nt][0], acc[mt][nt][1]);
            if (r + 8 < M)
                *(float2*)(C + (long)(r + 8) * N + col) =
                    make_float2(acc[mt][nt][2], acc[mt][nt][3]);
        }
    }
}

// ---------------------------------------------------------------------------
// Transpose: S[R,C] -> D[C,R], 32x32 tiles, block (32,8)
// ---------------------------------------------------------------------------
__global__ void transp(const float* __restrict__ S, float* __restrict__ D,
                       int R, int C)
{
    __shared__ float t[32][33];
    int bx = blockIdx.x * 32, by = blockIdx.y * 32;
    int x = threadIdx.x, y = threadIdx.y;
#pragma unroll
    for (int j = 0; j < 32; j += 8)
        t[y + j][x] = S[(long)(by + y + j) * C + bx + x];
    __syncthreads();
#pragma unroll
    for (int j = 0; j < 32; j += 8)
        D[(long)(bx + y + j) * R + by + x] = t[x][y + j];
}

// ---------------------------------------------------------------------------
// Flash attention for d_h = 64 (unchanged; passes, ~fp32 exact)
// ---------------------------------------------------------------------------
#define ALD 68

__global__ __launch_bounds__(256) void attn64(
    const float* __restrict__ Q, long qBatch,
    const float* __restrict__ Kp, const float* __restrict__ Vp, long kvBatch,
    int nkeys, float* __restrict__ Out, long oBatch)
{
    extern __shared__ float smf[];
    float* Qs = smf;
    float* Ks = Qs + 64 * ALD;
    float* Vs = Ks + 64 * ALD;
    float* Ps = Vs + 64 * ALD;
    float* mrow = Ps + 64 * ALD;
    float* lrow = mrow + 64;
    float* crow = lrow + 64;

    int tid = threadIdx.x;
    int h = blockIdx.y, b = blockIdx.z;
    int qtile = blockIdx.x;
    const float scale = 0.125f;

    const float* Qbase = Q + (long)b * qBatch + (long)qtile * 64 * DLAT + h * DHEAD;
    const float* Kbase = Kp + (long)b * kvBatch + h * DHEAD;
    const float* Vbase = Vp + (long)b * kvBatch + h * DHEAD;

#pragma unroll
    for (int i = 0; i < 16; i++) {
        int idx = tid + 256 * i;
        int q = idx >> 6, d = idx & 63;
        Qs[d * ALD + q] = Qbase[(long)q * DLAT + d] * scale;
    }
    if (tid < 64) { mrow[tid] = -1e30f; lrow[tid] = 0.0f; }
    __syncthreads();

    int tx = tid & 15, ty = tid >> 4;
    float o[4][4];
#pragma unroll
    for (int i = 0; i < 4; i++)
#pragma unroll
        for (int j = 0; j < 4; j++) o[i][j] = 0.0f;

    for (int k0 = 0; k0 < nkeys; k0 += 64) {
#pragma unroll
        for (int i = 0; i < 16; i++) {
            int idx = tid + 256 * i;
            int k = idx >> 6, d = idx & 63;
            float kv = Kbase[(long)(k0 + k) * DLAT + d];
            float vv = Vbase[(long)(k0 + k) * DLAT + d];
            Ks[d * ALD + k] = kv;
            Vs[k * ALD + d] = vv;
        }
        __syncthreads();

        float s[4][4];
#pragma unroll
        for (int i = 0; i < 4; i++)
#pragma unroll
            for (int j = 0; j < 4; j++) s[i][j] = 0.0f;
#pragma unroll
        for (int d = 0; d < 64; d++) {
            float4 qf = *(float4*)&Qs[d * ALD + ty * 4];
            float4 kf = *(float4*)&Ks[d * ALD + tx * 4];
            float qa[4] = {qf.x, qf.y, qf.z, qf.w};
            float ka[4] = {kf.x, kf.y, kf.z, kf.w};
#pragma unroll
            for (int ki = 0; ki < 4; ki++)
#pragma unroll
                for (int qj = 0; qj < 4; qj++)
                    s[ki][qj] += ka[ki] * qa[qj];
        }
#pragma unroll
        for (int ki = 0; ki < 4; ki++)
            *(float4*)&Ps[(tx * 4 + ki) * ALD + ty * 4] =
                make_float4(s[ki][0], s[ki][1], s[ki][2], s[ki][3]);
        __syncthreads();

        if (tid < 64) {
            int q = tid;
            float mold = mrow[q];
            float mx = mold;
            for (int k = 0; k < 64; k++) mx = fmaxf(mx, Ps[k * ALD + q]);
            float c = __expf(mold - mx);
            float l = lrow[q] * c;
            for (int k = 0; k < 64; k++) {
                float p = __expf(Ps[k * ALD + q] - mx);
                Ps[k * ALD + q] = p;
                l += p;
            }
            mrow[q] = mx; lrow[q] = l; crow[q] = c;
        }
        __syncthreads();

        float cq[4];
        *(float4*)cq = *(float4*)&crow[ty * 4];
#pragma unroll
        for (int i = 0; i < 4; i++)
#pragma unroll
            for (int j = 0; j < 4; j++) o[i][j] *= cq[i];

#pragma unroll 8
        for (int j = 0; j < 64; j++) {
            float4 pf = *(float4*)&Ps[j * ALD + ty * 4];
            float4 vf = *(float4*)&Vs[j * ALD + tx * 4];
            float pa[4] = {pf.x, pf.y, pf.z, pf.w};
            float va[4] = {vf.x, vf.y, vf.z, vf.w};
#pragma unroll
            for (int qi = 0; qi < 4; qi++)
#pragma unroll
                for (int dj = 0; dj < 4; dj++)
                    o[qi][dj] += pa[qi] * va[dj];
        }
        __syncthreads();
    }

    float lq[4];
    *(float4*)lq = *(float4*)&lrow[ty * 4];
    float* Obase = Out + (long)b * oBatch + (long)qtile * 64 * DLAT + h * DHEAD;
#pragma unroll
    for (int qi = 0; qi < 4; qi++) {
        float inv = 1.0f / lq[qi];
        int q = ty * 4 + qi;
        float* op = Obase + (long)q * DLAT + tx * 4;
        *(float4*)op = make_float4(o[qi][0] * inv, o[qi][1] * inv,
                                   o[qi][2] * inv, o[qi][3] * inv);
    }
}

// ---------------------------------------------------------------------------
// Host launch
// ---------------------------------------------------------------------------
static void launch_gemm_mma(const float* A, const float* Bt, float* C,
                            int M, int N, int K)
{
    dim3 grid(N / GBN, (M + GBM - 1) / GBM);
    gemm_mma<<<grid, 256, GEMM_SMEM>>>(A, Bt, C, M, N, K);
}

extern "C" void kernel_launch(void* const* d_in, const int* in_sizes, int n_in,
                              void* d_out, int out_size)
{
    const float* x       = (const float*)d_in[0];
    const float* L       = (const float*)d_in[1];
    const float* W_q_lat = (const float*)d_in[2];
    const float* W_k_in  = (const float*)d_in[3];
    const float* W_v_in  = (const float*)d_in[4];
    const float* W_q_in  = (const float*)d_in[5];
    const float* W_k_lat = (const float*)d_in[6];
    const float* W_v_lat = (const float*)d_in[7];
    const float* W_out   = (const float*)d_in[8];
    float* out = (float*)d_out;

    float* scratch = nullptr;
    cudaGetSymbolAddress((void**)&scratch, g_scratch);

    float* gK    = scratch + OFF_K;
    float* gV    = scratch + OFF_V;
    float* gQx   = scratch + OFF_QX;
    float* gXlat = scratch + OFF_XLAT;
    float* gQ1   = scratch + OFF_Q1;
    float* gZ    = scratch + OFF_Z;
    float* gZ2   = scratch + OFF_Z2;
    float* gQl   = scratch + OFF_QL;
    float* gKl   = scratch + OFF_KL;
    float* gVl   = scratch + OFF_VL;
    float* gKz   = scratch + OFF_KZ;
    float* gVz   = scratch + OFF_VZ;

    float* tWkin  = scratch + OFF_WKINT;
    float* tWvin  = scratch + OFF_WVINT;
    float* tWqin  = scratch + OFF_WQINT;
    float* tWqlat = scratch + OFF_WQLATT;
    float* tWklat = scratch + OFF_WKLATT;
    float* tWvlat = scratch + OFF_WVLATT;
    float* tWout  = scratch + OFF_WOUTT;

    const int ATTN_SMEM = (4 * 64 * ALD + 192) * 4;   // 70400 B
    cudaFuncSetAttribute(attn64, cudaFuncAttributeMaxDynamicSharedMemorySize,
                         ATTN_SMEM);
    cudaFuncSetAttribute(gemm_mma, cudaFuncAttributeMaxDynamicSharedMemorySize,
                         GEMM_SMEM);

    // --- Transpose all weights to [N, K] K-major ---
    {
        dim3 blk(32, 8);
        transp<<<dim3(DLAT / 32, DMODEL / 32), blk>>>(W_k_in, tWkin, DMODEL, DLAT);
        transp<<<dim3(DLAT / 32, DMODEL / 32), blk>>>(W_v_in, tWvin, DMODEL, DLAT);
        transp<<<dim3(DLAT / 32, DMODEL / 32), blk>>>(W_q_in, tWqin, DMODEL, DLAT);
        transp<<<dim3(DLAT / 32, DLAT / 32),   blk>>>(W_q_lat, tWqlat, DLAT, DLAT);
        transp<<<dim3(DLAT / 32, DLAT / 32),   blk>>>(W_k_lat, tWklat, DLAT, DLAT);
        transp<<<dim3(DLAT / 32, DLAT / 32),   blk>>>(W_v_lat, tWvlat, DLAT, DLAT);
        transp<<<dim3(DMODEL / 32, DLAT / 32), blk>>>(W_out, tWout, DLAT, DMODEL);
    }

    // --- Stage 0: big input projections ---
    launch_gemm_mma(x, tWkin, gK, BT, DLAT, DMODEL);
    launch_gemm_mma(x, tWvin, gV, BT, DLAT, DMODEL);
    launch_gemm_mma(x, tWqin, gQx, BT, DLAT, DMODEL);
    launch_gemm_mma(L, tWqlat, gQ1, NLAT, DLAT, DLAT);

    // --- Stage 1: latents attend to tokens ---
    {
        dim3 grid(1, NHEADS, BATCH);
        attn64<<<grid, 256, ATTN_SMEM>>>(gQ1, 0L, gK, gV,
                                         (long)TSEQ * DLAT, TSEQ,
                                         gZ, (long)NLAT * DLAT);
    }

    // --- Stage 2 projections ---
    launch_gemm_mma(gZ, tWqlat, gQl, BATCH * NLAT, DLAT, DLAT);
    launch_gemm_mma(gZ, tWklat, gKl, BATCH * NLAT, DLAT, DLAT);
    launch_gemm_mma(gZ, tWvlat, gVl, BATCH * NLAT, DLAT, DLAT);

    // --- Stage 2: latent self-attention ---
    {
        dim3 grid(1, NHEADS, BATCH);
        attn64<<<grid, 256, ATTN_SMEM>>>(gQl, (long)NLAT * DLAT, gKl, gVl,
                                         (long)NLAT * DLAT, NLAT,
                                         gZ2, (long)NLAT * DLAT);
    }

    // --- Stage 3 projections ---
    launch_gemm_mma(gZ2, tWklat, gKz, BATCH * NLAT, DLAT, DLAT);
    launch_gemm_mma(gZ2, tWvlat, gVz, BATCH * NLAT, DLAT, DLAT);

    // --- Stage 3: tokens attend to latents ---
    {
        dim3 grid(TSEQ / 64, NHEADS, BATCH);
        attn64<<<grid, 256, ATTN_SMEM>>>(gQx, (long)TSEQ * DLAT, gKz, gVz,
                                         (long)NLAT * DLAT, NLAT,
                                         gXlat, (long)TSEQ * DLAT);
    }

    // --- Output projection ---
    launch_gemm_mma(gXlat, tWout, out, BT, DMODEL, DLAT);
}

// round 10
// speedup vs baseline: 2.7540x; 1.0552x over previous
#include <cuda_runtime.h>
#include <cuda_bf16.h>
#include <cstdint>

// Problem constants
#define BATCH 4
#define TSEQ 4096
#define DMODEL 2048
#define NLAT 64
#define DLAT 1024
#define NHEADS 16
#define DHEAD 64
#define BT (BATCH * TSEQ)        // 16384
#define SPLITS 16                // stage-1 kv splits (4096/16 = 256 keys each)

// ---------------------------------------------------------------------------
// Scratch offsets (floats)
// ---------------------------------------------------------------------------
#define OFF_K      0L
#define OFF_V      16777216L
#define OFF_QX     33554432L
#define OFF_XLAT   50331648L
#define OFF_Q1     67108864L
#define OFF_Z      67174400L
#define OFF_Z2     67436544L
#define OFF_QL     67698688L
#define OFF_KL     67960832L
#define OFF_VL     68222976L
#define OFF_KZ     68485120L
#define OFF_VZ     68747264L
// transposed weights [N,K]
#define OFF_WKINT  69009408L
#define OFF_WVINT  71106560L
#define OFF_WQINT  73203712L
#define OFF_WQLATT 75300864L
#define OFF_WKLATT 76349440L
#define OFF_WVLATT 77398016L
#define OFF_WOUTT  78446592L
// stage-1 split-K partials
#define OFF_PO     80543744L     // [16][4][16][64][64]
#define OFF_PM     84738048L     // [16][4][16][64]
#define OFF_PL     84803584L
#define SCRATCH_FLOATS 84869120L

__device__ float g_scratch[SCRATCH_FLOATS];

__device__ __forceinline__ uint32_t tf32r(float x) {
    uint32_t r;
    asm("cvt.rna.tf32.f32 %0, %1;" : "=r"(r) : "f"(x));
    return r;
}

// ---------------------------------------------------------------------------
// tf32 mma.sync GEMM: C[M,N] = A[M,K] * Bt[N,K]^T (Bt is [N,K] K-major).
// CTA tile 128x128, BK=16, 256 threads (8 warps, 4x2), warp tile 32x64.
// ---------------------------------------------------------------------------
#define GBM 128
#define GBN 128
#define GBK 16
#define LDSA 20
#define BUF_FLOATS (GBM * LDSA)
#define GEMM_SMEM (2 * 2 * BUF_FLOATS * 4)   // 40960 bytes

__global__ __launch_bounds__(256, 2) void gemm_mma(
    const float* __restrict__ A, const float* __restrict__ Bt,
    float* __restrict__ C, int M, int N, int K)
{
    extern __shared__ float sm[];
    const int tid = threadIdx.x;
    const int wid = tid >> 5, lane = tid & 31;
    const int grp = lane >> 2, qc = lane & 3;
    const int warp_m = wid & 3, warp_n = wid >> 2;
    const int row0 = blockIdx.y * GBM;
    const int col0 = blockIdx.x * GBN;
    const int nchunks = K / GBK;

    float acc[2][8][4];
#pragma unroll
    for (int i = 0; i < 2; i++)
#pragma unroll
        for (int j = 0; j < 8; j++)
#pragma unroll
            for (int l = 0; l < 4; l++) acc[i][j][l] = 0.0f;

    float4 apre[2], bpre[2];
    const float* Abase = A + (long)row0 * K;
    const float* Bbase = Bt + (long)col0 * K;

#pragma unroll
    for (int i = 0; i < 2; i++) {
        int f4 = tid + 256 * i;
        int r = f4 >> 2, cc = (f4 & 3) * 4;
        apre[i] = (row0 + r < M) ? *(const float4*)(Abase + (long)r * K + cc)
                                 : make_float4(0.f, 0.f, 0.f, 0.f);
        bpre[i] = *(const float4*)(Bbase + (long)r * K + cc);
    }

    for (int c = 0; c < nchunks; c++) {
        float* As = sm + (c & 1) * (2 * BUF_FLOATS);
        float* Bs = As + BUF_FLOATS;

#pragma unroll
        for (int i = 0; i < 2; i++) {
            int f4 = tid + 256 * i;
            int r = f4 >> 2, cc = (f4 & 3) * 4;
            uint32_t* pa = (uint32_t*)(As + r * LDSA + cc);
            pa[0] = tf32r(apre[i].x); pa[1] = tf32r(apre[i].y);
            pa[2] = tf32r(apre[i].z); pa[3] = tf32r(apre[i].w);
            uint32_t* pb = (uint32_t*)(Bs + r * LDSA + cc);
            pb[0] = tf32r(bpre[i].x); pb[1] = tf32r(bpre[i].y);
            pb[2] = tf32r(bpre[i].z); pb[3] = tf32r(bpre[i].w);
        }
        __syncthreads();

        if (c + 1 < nchunks) {
            const float* An = Abase + (c + 1) * GBK;
            const float* Bn = Bbase + (c + 1) * GBK;
#pragma unroll
            for (int i = 0; i < 2; i++) {
                int f4 = tid + 256 * i;
                int r = f4 >> 2, cc = (f4 & 3) * 4;
                apre[i] = (row0 + r < M) ? *(const float4*)(An + (long)r * K + cc)
                                         : make_float4(0.f, 0.f, 0.f, 0.f);
                bpre[i] = *(const float4*)(Bn + (long)r * K + cc);
            }
        }

#pragma unroll
        for (int ks = 0; ks < 2; ks++) {
            int k0 = ks * 8;
            uint32_t a[2][4], b[8][2];
#pragma unroll
            for (int mt = 0; mt < 2; mt++) {
                int r = warp_m * 32 + mt * 16 + grp;
                const uint32_t* p0 = (const uint32_t*)(As + r * LDSA + k0 + qc);
                const uint32_t* p1 = (const uint32_t*)(As + (r + 8) * LDSA + k0 + qc);
                a[mt][0] = p0[0]; a[mt][2] = p0[4];
                a[mt][1] = p1[0]; a[mt][3] = p1[4];
            }
#pragma unroll
            for (int nt = 0; nt < 8; nt++) {
                int r = warp_n * 64 + nt * 8 + grp;
                const uint32_t* p = (const uint32_t*)(Bs + r * LDSA + k0 + qc);
                b[nt][0] = p[0]; b[nt][1] = p[4];
            }
#pragma unroll
            for (int mt = 0; mt < 2; mt++)
#pragma unroll
                for (int nt = 0; nt < 8; nt++)
                    asm volatile(
                        "mma.sync.aligned.m16n8k8.row.col.f32.tf32.tf32.f32 "
                        "{%0,%1,%2,%3}, {%4,%5,%6,%7}, {%8,%9}, {%0,%1,%2,%3};"
                        : "+f"(acc[mt][nt][0]), "+f"(acc[mt][nt][1]),
                          "+f"(acc[mt][nt][2]), "+f"(acc[mt][nt][3])
                        : "r"(a[mt][0]), "r"(a[mt][1]), "r"(a[mt][2]), "r"(a[mt][3]),
                          "r"(b[nt][0]), "r"(b[nt][1]));
        }
        __syncthreads();
    }

#pragma unroll
    for (int mt = 0; mt < 2; mt++) {
        int r = row0 + warp_m * 32 + mt * 16 + grp;
#pragma unroll
        for (int nt = 0; nt < 8; nt++) {
            int col = col0 + warp_n * 64 + nt * 8 + qc * 2;
            if (r < M)
                *(float2*)(C + (long)r * N + col) =
                    make_float2(acc[mt][nt][0], acc[mt][nt][1]);
            if (r + 8 < M)
                *(float2*)(C + (long)(r + 8) * N + col) =
                    make_float2(acc[mt][nt][2], acc[mt][nt][3]);
        }
    }
}

// ---------------------------------------------------------------------------
// Batched transpose of all 7 weights in ONE launch. blockIdx.z selects which.
// ---------------------------------------------------------------------------
__global__ void transp_all(
    const float* __restrict__ W_q_lat, const float* __restrict__ W_k_in,
    const float* __restrict__ W_v_in,  const float* __restrict__ W_q_in,
    const float* __restrict__ W_k_lat, const float* __restrict__ W_v_lat,
    const float* __restrict__ W_out,   float* __restrict__ scr)
{
    const float* S; float* D; int R, C;
    switch (blockIdx.z) {
        case 0: S = W_k_in;  D = scr + OFF_WKINT;  R = DMODEL; C = DLAT;   break;
        case 1: S = W_v_in;  D = scr + OFF_WVINT;  R = DMODEL; C = DLAT;   break;
        case 2: S = W_q_in;  D = scr + OFF_WQINT;  R = DMODEL; C = DLAT;   break;
        case 3: S = W_q_lat; D = scr + OFF_WQLATT; R = DLAT;   C = DLAT;   break;
        case 4: S = W_k_lat; D = scr + OFF_WKLATT; R = DLAT;   C = DLAT;   break;
        case 5: S = W_v_lat; D = scr + OFF_WVLATT; R = DLAT;   C = DLAT;   break;
        default: S = W_out;  D = scr + OFF_WOUTT;  R = DLAT;   C = DMODEL; break;
    }
    int bx = blockIdx.x * 32, by = blockIdx.y * 32;
    if (bx >= C || by >= R) return;
    __shared__ float t[32][33];
    int x = threadIdx.x, y = threadIdx.y;
#pragma unroll
    for (int j = 0; j < 32; j += 8)
        t[y + j][x] = S[(long)(by + y + j) * C + bx + x];
    __syncthreads();
#pragma unroll
    for (int j = 0; j < 32; j += 8)
        D[(long)(bx + y + j) * R + by + x] = t[x][y + j];
}

// ---------------------------------------------------------------------------
// Flash attention for d_h = 64 (stages 2 and 3)
// ---------------------------------------------------------------------------
#define ALD 68

__global__ __launch_bounds__(256) void attn64(
    const float* __restrict__ Q, long qBatch,
    const float* __restrict__ Kp, const float* __restrict__ Vp, long kvBatch,
    int nkeys, float* __restrict__ Out, long oBatch)
{
    extern __shared__ float smf[];
    float* Qs = smf;
    float* Ks = Qs + 64 * ALD;
    float* Vs = Ks + 64 * ALD;
    float* Ps = Vs + 64 * ALD;
    float* mrow = Ps + 64 * ALD;
    float* lrow = mrow + 64;
    float* crow = lrow + 64;

    int tid = threadIdx.x;
    int h = blockIdx.y, b = blockIdx.z;
    int qtile = blockIdx.x;
    const float scale = 0.125f;

    const float* Qbase = Q + (long)b * qBatch + (long)qtile * 64 * DLAT + h * DHEAD;
    const float* Kbase = Kp + (long)b * kvBatch + h * DHEAD;
    const float* Vbase = Vp + (long)b * kvBatch + h * DHEAD;

#pragma unroll
    for (int i = 0; i < 16; i++) {
        int idx = tid + 256 * i;
        int q = idx >> 6, d = idx & 63;
        Qs[d * ALD + q] = Qbase[(long)q * DLAT + d] * scale;
    }
    if (tid < 64) { mrow[tid] = -1e30f; lrow[tid] = 0.0f; }
    __syncthreads();

    int tx = tid & 15, ty = tid >> 4;
    float o[4][4];
#pragma unroll
    for (int i = 0; i < 4; i++)
#pragma unroll
        for (int j = 0; j < 4; j++) o[i][j] = 0.0f;

    for (int k0 = 0; k0 < nkeys; k0 += 64) {
#pragma unroll
        for (int i = 0; i < 16; i++) {
            int idx = tid + 256 * i;
            int k = idx >> 6, d = idx & 63;
            float kv = Kbase[(long)(k0 + k) * DLAT + d];
            float vv = Vbase[(long)(k0 + k) * DLAT + d];
            Ks[d * ALD + k] = kv;
            Vs[k * ALD + d] = vv;
        }
        __syncthreads();

        float s[4][4];
#pragma unroll
        for (int i = 0; i < 4; i++)
#pragma unroll
            for (int j = 0; j < 4; j++) s[i][j] = 0.0f;
#pragma unroll
        for (int d = 0; d < 64; d++) {
            float4 qf = *(float4*)&Qs[d * ALD + ty * 4];
            float4 kf = *(float4*)&Ks[d * ALD + tx * 4];
            float qa[4] = {qf.x, qf.y, qf.z, qf.w};
            float ka[4] = {kf.x, kf.y, kf.z, kf.w};
#pragma unroll
            for (int ki = 0; ki < 4; ki++)
#pragma unroll
                for (int qj = 0; qj < 4; qj++)
                    s[ki][qj] += ka[ki] * qa[qj];
        }
#pragma unroll
        for (int ki = 0; ki < 4; ki++)
            *(float4*)&Ps[(tx * 4 + ki) * ALD + ty * 4] =
                make_float4(s[ki][0], s[ki][1], s[ki][2], s[ki][3]);
        __syncthreads();

        if (tid < 64) {
            int q = tid;
            float mold = mrow[q];
            float mx = mold;
            for (int k = 0; k < 64; k++) mx = fmaxf(mx, Ps[k * ALD + q]);
            float c = __expf(mold - mx);
            float l = lrow[q] * c;
            for (int k = 0; k < 64; k++) {
                float p = __expf(Ps[k * ALD + q] - mx);
                Ps[k * ALD + q] = p;
                l += p;
            }
            mrow[q] = mx; lrow[q] = l; crow[q] = c;
        }
        __syncthreads();

        float cq[4];
        *(float4*)cq = *(float4*)&crow[ty * 4];
#pragma unroll
        for (int i = 0; i < 4; i++)
#pragma unroll
            for (int j = 0; j < 4; j++) o[i][j] *= cq[i];

#pragma unroll 8
        for (int j = 0; j < 64; j++) {
            float4 pf = *(float4*)&Ps[j * ALD + ty * 4];
            float4 vf = *(float4*)&Vs[j * ALD + tx * 4];
            float pa[4] = {pf.x, pf.y, pf.z, pf.w};
            float va[4] = {vf.x, vf.y, vf.z, vf.w};
#pragma unroll
            for (int qi = 0; qi < 4; qi++)
#pragma unroll
                for (int dj = 0; dj < 4; dj++)
                    o[qi][dj] += pa[qi] * va[dj];
        }
        __syncthreads();
    }

    float lq[4];
    *(float4*)lq = *(float4*)&lrow[ty * 4];
    float* Obase = Out + (long)b * oBatch + (long)qtile * 64 * DLAT + h * DHEAD;
#pragma unroll
    for (int qi = 0; qi < 4; qi++) {
        float inv = 1.0f / lq[qi];
        int q = ty * 4 + qi;
        float* op = Obase + (long)q * DLAT + tx * 4;
        *(float4*)op = make_float4(o[qi][0] * inv, o[qi][1] * inv,
                                   o[qi][2] * inv, o[qi][3] * inv);
    }
}

// ---------------------------------------------------------------------------
// Stage-1 split-K attention: grid (SPLITS, NHEADS, BATCH).
// Each block: 64 latent queries x 256 keys -> unnormalized partial O + (m, l).
// ---------------------------------------------------------------------------
__global__ __launch_bounds__(256) void attn1_split(
    const float* __restrict__ Q,       // gQ1 [64, 1024], shared across batch
    const float* __restrict__ Kp, const float* __restrict__ Vp,
    float* __restrict__ po, float* __restrict__ pm, float* __restrict__ pl)
{
    extern __shared__ float smf[];
    float* Qs = smf;
    float* Ks = Qs + 64 * ALD;
    float* Vs = Ks + 64 * ALD;
    float* Ps = Vs + 64 * ALD;
    float* mrow = Ps + 64 * ALD;
    float* lrow = mrow + 64;
    float* crow = lrow + 64;

    int tid = threadIdx.x;
    int s = blockIdx.x, h = blockIdx.y, b = blockIdx.z;
    const float scale = 0.125f;

    const float* Qbase = Q + h * DHEAD;
    const float* Kbase = Kp + (long)b * TSEQ * DLAT + h * DHEAD;
    const float* Vbase = Vp + (long)b * TSEQ * DLAT + h * DHEAD;
    const int key0 = s * (TSEQ / SPLITS);

#pragma unroll
    for (int i = 0; i < 16; i++) {
        int idx = tid + 256 * i;
        int q = idx >> 6, d = idx & 63;
        Qs[d * ALD + q] = Qbase[(long)q * DLAT + d] * scale;
    }
    if (tid < 64) { mrow[tid] = -1e30f; lrow[tid] = 0.0f; }
    __syncthreads();

    int tx = tid & 15, ty = tid >> 4;
    float o[4][4];
#pragma unroll
    for (int i = 0; i < 4; i++)
#pragma unroll
        for (int j = 0; j < 4; j++) o[i][j] = 0.0f;

    for (int kc = 0; kc < TSEQ / SPLITS; kc += 64) {
        int k0 = key0 + kc;
#pragma unroll
        for (int i = 0; i < 16; i++) {
            int idx = tid + 256 * i;
            int k = idx >> 6, d = idx & 63;
            Ks[d * ALD + k] = Kbase[(long)(k0 + k) * DLAT + d];
            Vs[k * ALD + d] = Vbase[(long)(k0 + k) * DLAT + d];
        }
        __syncthreads();

        float sacc[4][4];
#pragma unroll
        for (int i = 0; i < 4; i++)
#pragma unroll
            for (int j = 0; j < 4; j++) sacc[i][j] = 0.0f;
#pragma unroll
        for (int d = 0; d < 64; d++) {
            float4 qf = *(float4*)&Qs[d * ALD + ty * 4];
            float4 kf = *(float4*)&Ks[d * ALD + tx * 4];
            float qa[4] = {qf.x, qf.y, qf.z, qf.w};
            float ka[4] = {kf.x, kf.y, kf.z, kf.w};
#pragma unroll
            for (int ki = 0; ki < 4; ki++)
#pragma unroll
                for (int qj = 0; qj < 4; qj++)
                    sacc[ki][qj] += ka[ki] * qa[qj];
        }
#pragma unroll
        for (int ki = 0; ki < 4; ki++)
            *(float4*)&Ps[(tx * 4 + ki) * ALD + ty * 4] =
                make_float4(sacc[ki][0], sacc[ki][1], sacc[ki][2], sacc[ki][3]);
        __syncthreads();

        if (tid < 64) {
            int q = tid;
            float mold = mrow[q];
            float mx = mold;
            for (int k = 0; k < 64; k++) mx = fmaxf(mx, Ps[k * ALD + q]);
            float c = __expf(mold - mx);
            float l = lrow[q] * c;
            for (int k = 0; k < 64; k++) {
                float p = __expf(Ps[k * ALD + q] - mx);
                Ps[k * ALD + q] = p;
                l += p;
            }
            mrow[q] = mx; lrow[q] = l; crow[q] = c;
        }
        __syncthreads();

        float cq[4];
        *(float4*)cq = *(float4*)&crow[ty * 4];
#pragma unroll
        for (int i = 0; i < 4; i++)
#pragma unroll
            for (int j = 0; j < 4; j++) o[i][j] *= cq[i];

#pragma unroll 8
        for (int j = 0; j < 64; j++) {
            float4 pf = *(float4*)&Ps[j * ALD + ty * 4];
            float4 vf = *(float4*)&Vs[j * ALD + tx * 4];
            float pa[4] = {pf.x, pf.y, pf.z, pf.w};
            float va[4] = {vf.x, vf.y, vf.z, vf.w};
#pragma unroll
            for (int qi = 0; qi < 4; qi++)
#pragma unroll
                for (int dj = 0; dj < 4; dj++)
                    o[qi][dj] += pa[qi] * va[dj];
        }
        __syncthreads();
    }

    // Write unnormalized partials
    long base = ((((long)s * BATCH + b) * NHEADS + h) * 64);
    float* pob = po + base * 64;
#pragma unroll
    for (int qi = 0; qi < 4; qi++) {
        int q = ty * 4 + qi;
        *(float4*)(pob + (long)q * 64 + tx * 4) =
            make_float4(o[qi][0], o[qi][1], o[qi][2], o[qi][3]);
    }
    if (tid < 64) {
        pm[base + tid] = mrow[tid];
        pl[base + tid] = lrow[tid];
    }
}

// ---------------------------------------------------------------------------
// Combine stage-1 partials -> z[b][q][h*64+d]. grid (NHEADS, BATCH).
// ---------------------------------------------------------------------------
__global__ __launch_bounds__(256) void combine1(
    const float* __restrict__ po, const float* __restrict__ pm,
    const float* __restrict__ pl, float* __restrict__ z)
{
    __shared__ float coef[SPLITS][64];
    int tid = threadIdx.x;
    int h = blockIdx.x, b = blockIdx.y;

    if (tid < 64) {
        int q = tid;
        float mx = -1e30f;
        float ms[SPLITS];
#pragma unroll
        for (int s = 0; s < SPLITS; s++) {
            ms[s] = pm[((((long)s * BATCH + b) * NHEADS + h) * 64) + q];
            mx = fmaxf(mx, ms[s]);
        }
        float lsum = 0.0f;
        float es[SPLITS];
#pragma unroll
        for (int s = 0; s < SPLITS; s++) {
            es[s] = __expf(ms[s] - mx);
            lsum += es[s] * pl[((((long)s * BATCH + b) * NHEADS + h) * 64) + q];
        }
        float inv = 1.0f / lsum;
#pragma unroll
        for (int s = 0; s < SPLITS; s++) coef[s][q] = es[s] * inv;
    }
    __syncthreads();

#pragma unroll
    for (int i = 0; i < 16; i++) {
        int idx = tid + 256 * i;       // 0..4095
        int q = idx >> 6, d = idx & 63;
        float sum = 0.0f;
#pragma unroll
        for (int s = 0; s < SPLITS; s++) {
            sum += coef[s][q] *
                   po[(((((long)s * BATCH + b) * NHEADS + h) * 64) + q) * 64 + d];
        }
        z[(long)b * NLAT * DLAT + (long)q * DLAT + h * DHEAD + d] = sum;
    }
}

// ---------------------------------------------------------------------------
// Host launch
// ---------------------------------------------------------------------------
static void launch_gemm_mma(const float* A, const float* Bt, float* C,
                            int M, int N, int K)
{
    dim3 grid(N / GBN, (M + GBM - 1) / GBM);
    gemm_mma<<<grid, 256, GEMM_SMEM>>>(A, Bt, C, M, N, K);
}

extern "C" void kernel_launch(void* const* d_in, const int* in_sizes, int n_in,
                              void* d_out, int out_size)
{
    const float* x       = (const float*)d_in[0];
    const float* L       = (const float*)d_in[1];
    const float* W_q_lat = (const float*)d_in[2];
    const float* W_k_in  = (const float*)d_in[3];
    const float* W_v_in  = (const float*)d_in[4];
    const float* W_q_in  = (const float*)d_in[5];
    const float* W_k_lat = (const float*)d_in[6];
    const float* W_v_lat = (const float*)d_in[7];
    const float* W_out   = (const float*)d_in[8];
    float* out = (float*)d_out;

    float* scratch = nullptr;
    cudaGetSymbolAddress((void**)&scratch, g_scratch);

    float* gK    = scratch + OFF_K;
    float* gV    = scratch + OFF_V;
    float* gQx   = scratch + OFF_QX;
    float* gXlat = scratch + OFF_XLAT;
    float* gQ1   = scratch + OFF_Q1;
    float* gZ    = scratch + OFF_Z;
    float* gZ2   = scratch + OFF_Z2;
    float* gQl   = scratch + OFF_QL;
    float* gKl   = scratch + OFF_KL;
    float* gVl   = scratch + OFF_VL;
    float* gKz   = scratch + OFF_KZ;
    float* gVz   = scratch + OFF_VZ;
    float* gPo   = scratch + OFF_PO;
    float* gPm   = scratch + OFF_PM;
    float* gPl   = scratch + OFF_PL;

    float* tWkin  = scratch + OFF_WKINT;
    float* tWvin  = scratch + OFF_WVINT;
    float* tWqin  = scratch + OFF_WQINT;
    float* tWqlat = scratch + OFF_WQLATT;
    float* tWklat = scratch + OFF_WKLATT;
    float* tWvlat = scratch + OFF_WVLATT;
    float* tWout  = scratch + OFF_WOUTT;

    const int ATTN_SMEM = (4 * 64 * ALD + 192) * 4;   // 70400 B
    cudaFuncSetAttribute(attn64, cudaFuncAttributeMaxDynamicSharedMemorySize,
                         ATTN_SMEM);
    cudaFuncSetAttribute(attn1_split, cudaFuncAttributeMaxDynamicSharedMemorySize,
                         ATTN_SMEM);
    cudaFuncSetAttribute(gemm_mma, cudaFuncAttributeMaxDynamicSharedMemorySize,
                         GEMM_SMEM);

    // (1) all transposes in one launch
    transp_all<<<dim3(64, 64, 7), dim3(32, 8)>>>(
        W_q_lat, W_k_in, W_v_in, W_q_in, W_k_lat, W_v_lat, W_out, scratch);

    // (2) q1  (3) K  (4) V  (5)(6) Qx in two halves -> launch #6 is a big gemm
    launch_gemm_mma(L, tWqlat, gQ1, NLAT, DLAT, DLAT);
    launch_gemm_mma(x, tWkin, gK, BT, DLAT, DMODEL);
    launch_gemm_mma(x, tWvin, gV, BT, DLAT, DMODEL);
    launch_gemm_mma(x, tWqin, gQx, BT / 2, DLAT, DMODEL);
    launch_gemm_mma(x + (long)(BT / 2) * DMODEL, tWqin,
                    gQx + (long)(BT / 2) * DLAT, BT / 2, DLAT, DMODEL);

    // Stage 1: split-K attention + combine
    attn1_split<<<dim3(SPLITS, NHEADS, BATCH), 256, ATTN_SMEM>>>(
        gQ1, gK, gV, gPo, gPm, gPl);
    combine1<<<dim3(NHEADS, BATCH), 256>>>(gPo, gPm, gPl, gZ);

    // Stage 2 projections
    launch_gemm_mma(gZ, tWqlat, gQl, BATCH * NLAT, DLAT, DLAT);
    launch_gemm_mma(gZ, tWklat, gKl, BATCH * NLAT, DLAT, DLAT);
    launch_gemm_mma(gZ, tWvlat, gVl, BATCH * NLAT, DLAT, DLAT);

    // Stage 2: latent self-attention
    {
        dim3 grid(1, NHEADS, BATCH);
        attn64<<<grid, 256, ATTN_SMEM>>>(gQl, (long)NLAT * DLAT, gKl, gVl,
                                         (long)NLAT * DLAT, NLAT,
                                         gZ2, (long)NLAT * DLAT);
    }

    // Stage 3 projections
    launch_gemm_mma(gZ2, tWklat, gKz, BATCH * NLAT, DLAT, DLAT);
    launch_gemm_mma(gZ2, tWvlat, gVz, BATCH * NLAT, DLAT, DLAT);

    // Stage 3: tokens attend to latents
    {
        dim3 grid(TSEQ / 64, NHEADS, BATCH);
        attn64<<<grid, 256, ATTN_SMEM>>>(gQx, (long)TSEQ * DLAT, gKz, gVz,
                                         (long)NLAT * DLAT, NLAT,
                                         gXlat, (long)TSEQ * DLAT);
    }

    // Output projection
    launch_gemm_mma(gXlat, tWout, out, BT, DMODEL, DLAT);
}

// round 11
// speedup vs baseline: 3.0260x; 1.0988x over previous
#include <cuda_runtime.h>
#include <cuda_bf16.h>
#include <cstdint>

// Problem constants
#define BATCH 4
#define TSEQ 4096
#define DMODEL 2048
#define NLAT 64
#define DLAT 1024
#define NHEADS 16
#define DHEAD 64
#define BT (BATCH * TSEQ)        // 16384
#define SPLITS 16                // stage-1 kv splits (4096/16 = 256 keys each)

// ---------------------------------------------------------------------------
// Scratch offsets (floats)
// ---------------------------------------------------------------------------
#define OFF_K      0L
#define OFF_V      16777216L
#define OFF_QX     33554432L
#define OFF_XLAT   50331648L
#define OFF_Q1     67108864L
#define OFF_Z      67174400L
#define OFF_Z2     67436544L
#define OFF_QL     67698688L
#define OFF_KL     67960832L
#define OFF_VL     68222976L
#define OFF_KZ     68485120L
#define OFF_VZ     68747264L
// transposed weights [N,K]
#define OFF_WKINT  69009408L
#define OFF_WVINT  71106560L
#define OFF_WQINT  73203712L
#define OFF_WQLATT 75300864L
#define OFF_WKLATT 76349440L
#define OFF_WVLATT 77398016L
#define OFF_WOUTT  78446592L
// stage-1 split-K partials
#define OFF_PO     80543744L     // [16][4][16][64][64]
#define OFF_PM     84738048L     // [16][4][16][64]
#define OFF_PL     84803584L
#define SCRATCH_FLOATS 84869120L

__device__ float g_scratch[SCRATCH_FLOATS];

__device__ __forceinline__ uint32_t tf32r(float x) {
    uint32_t r;
    asm("cvt.rna.tf32.f32 %0, %1;" : "=r"(r) : "f"(x));
    return r;
}

// ---------------------------------------------------------------------------
// tf32 mma.sync GEMM: C[M,N] = A[M,K] * Bt[N,K]^T (Bt is [N,K] K-major).
// CTA tile 128x128, BK=16, 128 threads (4 warps, 2x2), warp tile 64x64.
// Per ks-slice: 16 A-LDS + 16 B-LDS feed 32 MMAs (1.0 LDS/MMA).
// Double-buffered SMEM, register prefetch, STS.128 fills.
// ---------------------------------------------------------------------------
#define GBM 128
#define GBN 128
#define GBK 16
#define LDSA 20
#define BUF_FLOATS (GBM * LDSA)
#define GEMM_SMEM (2 * 2 * BUF_FLOATS * 4)   // 40960 bytes

__global__ __launch_bounds__(128, 2) void gemm_mma(
    const float* __restrict__ A, const float* __restrict__ Bt,
    float* __restrict__ C, int M, int N, int K)
{
    extern __shared__ float sm[];
    const int tid = threadIdx.x;
    const int wid = tid >> 5, lane = tid & 31;
    const int grp = lane >> 2, qc = lane & 3;
    const int warp_m = wid & 1, warp_n = wid >> 1;   // 2x2 warps
    const int row0 = blockIdx.y * GBM;
    const int col0 = blockIdx.x * GBN;
    const int nchunks = K / GBK;

    float acc[4][8][4];
#pragma unroll
    for (int i = 0; i < 4; i++)
#pragma unroll
        for (int j = 0; j < 8; j++)
#pragma unroll
            for (int l = 0; l < 4; l++) acc[i][j][l] = 0.0f;

    // Per-thread global-load mapping: 4 float4 for A, 4 for B per chunk.
    // chunk = 128 rows x 16 floats = 512 float4; f4 = tid + 128*i.
    float4 apre[4], bpre[4];
    const float* Abase = A + (long)row0 * K;
    const float* Bbase = Bt + (long)col0 * K;

#pragma unroll
    for (int i = 0; i < 4; i++) {
        int f4 = tid + 128 * i;
        int r = f4 >> 2, cc = (f4 & 3) * 4;
        apre[i] = (row0 + r < M) ? *(const float4*)(Abase + (long)r * K + cc)
                                 : make_float4(0.f, 0.f, 0.f, 0.f);
        bpre[i] = *(const float4*)(Bbase + (long)r * K + cc);
    }

    for (int c = 0; c < nchunks; c++) {
        float* As = sm + (c & 1) * (2 * BUF_FLOATS);
        float* Bs = As + BUF_FLOATS;

        // store prefetched chunk (tf32-rounded), vectorized STS.128
#pragma unroll
        for (int i = 0; i < 4; i++) {
            int f4 = tid + 128 * i;
            int r = f4 >> 2, cc = (f4 & 3) * 4;
            uint32_t a0 = tf32r(apre[i].x), a1 = tf32r(apre[i].y);
            uint32_t a2 = tf32r(apre[i].z), a3 = tf32r(apre[i].w);
            asm volatile("st.shared.v4.b32 [%0], {%1,%2,%3,%4};"
                :: "l"((void*)(As + r * LDSA + cc)),
                   "r"(a0), "r"(a1), "r"(a2), "r"(a3) : "memory");
            uint32_t b0 = tf32r(bpre[i].x), b1 = tf32r(bpre[i].y);
            uint32_t b2 = tf32r(bpre[i].z), b3 = tf32r(bpre[i].w);
            asm volatile("st.shared.v4.b32 [%0], {%1,%2,%3,%4};"
                :: "l"((void*)(Bs + r * LDSA + cc)),
                   "r"(b0), "r"(b1), "r"(b2), "r"(b3) : "memory");
        }
        __syncthreads();

        // prefetch next chunk
        if (c + 1 < nchunks) {
            const float* An = Abase + (c + 1) * GBK;
            const float* Bn = Bbase + (c + 1) * GBK;
#pragma unroll
            for (int i = 0; i < 4; i++) {
                int f4 = tid + 128 * i;
                int r = f4 >> 2, cc = (f4 & 3) * 4;
                apre[i] = (row0 + r < M) ? *(const float4*)(An + (long)r * K + cc)
                                         : make_float4(0.f, 0.f, 0.f, 0.f);
                bpre[i] = *(const float4*)(Bn + (long)r * K + cc);
            }
        }

        // compute: 2 k-slices of 8; 64x64 warp tile = 32 MMAs per slice
#pragma unroll
        for (int ks = 0; ks < 2; ks++) {
            int k0 = ks * 8;
            uint32_t a[4][4], b[8][2];
#pragma unroll
            for (int mt = 0; mt < 4; mt++) {
                int r = warp_m * 64 + mt * 16 + grp;
                const uint32_t* p0 = (const uint32_t*)(As + r * LDSA + k0 + qc);
                const uint32_t* p1 = (const uint32_t*)(As + (r + 8) * LDSA + k0 + qc);
                a[mt][0] = p0[0]; a[mt][2] = p0[4];
                a[mt][1] = p1[0]; a[mt][3] = p1[4];
            }
#pragma unroll
            for (int nt = 0; nt < 8; nt++) {
                int r = warp_n * 64 + nt * 8 + grp;
                const uint32_t* p = (const uint32_t*)(Bs + r * LDSA + k0 + qc);
                b[nt][0] = p[0]; b[nt][1] = p[4];
            }
#pragma unroll
            for (int mt = 0; mt < 4; mt++)
#pragma unroll
                for (int nt = 0; nt < 8; nt++)
                    asm volatile(
                        "mma.sync.aligned.m16n8k8.row.col.f32.tf32.tf32.f32 "
                        "{%0,%1,%2,%3}, {%4,%5,%6,%7}, {%8,%9}, {%0,%1,%2,%3};"
                        : "+f"(acc[mt][nt][0]), "+f"(acc[mt][nt][1]),
                          "+f"(acc[mt][nt][2]), "+f"(acc[mt][nt][3])
                        : "r"(a[mt][0]), "r"(a[mt][1]), "r"(a[mt][2]), "r"(a[mt][3]),
                          "r"(b[nt][0]), "r"(b[nt][1]));
        }
        __syncthreads();
    }

    // Epilogue
#pragma unroll
    for (int mt = 0; mt < 4; mt++) {
        int r = row0 + warp_m * 64 + mt * 16 + grp;
#pragma unroll
        for (int nt = 0; nt < 8; nt++) {
            int col = col0 + warp_n * 64 + nt * 8 + qc * 2;
            if (r < M)
                *(float2*)(C + (long)r * N + col) =
                    make_float2(acc[mt][nt][0], acc[mt][nt][1]);
            if (r + 8 < M)
                *(float2*)(C + (long)(r + 8) * N + col) =
                    make_float2(acc[mt][nt][2], acc[mt][nt][3]);
        }
    }
}

// ---------------------------------------------------------------------------
// Batched transpose of all 7 weights in ONE launch. blockIdx.z selects which.
// ---------------------------------------------------------------------------
__global__ void transp_all(
    const float* __restrict__ W_q_lat, const float* __restrict__ W_k_in,
    const float* __restrict__ W_v_in,  const float* __restrict__ W_q_in,
    const float* __restrict__ W_k_lat, const float* __restrict__ W_v_lat,
    const float* __restrict__ W_out,   float* __restrict__ scr)
{
    const float* S; float* D; int R, C;
    switch (blockIdx.z) {
        case 0: S = W_k_in;  D = scr + OFF_WKINT;  R = DMODEL; C = DLAT;   break;
        case 1: S = W_v_in;  D = scr + OFF_WVINT;  R = DMODEL; C = DLAT;   break;
        case 2: S = W_q_in;  D = scr + OFF_WQINT;  R = DMODEL; C = DLAT;   break;
        case 3: S = W_q_lat; D = scr + OFF_WQLATT; R = DLAT;   C = DLAT;   break;
        case 4: S = W_k_lat; D = scr + OFF_WKLATT; R = DLAT;   C = DLAT;   break;
        case 5: S = W_v_lat; D = scr + OFF_WVLATT; R = DLAT;   C = DLAT;   break;
        default: S = W_out;  D = scr + OFF_WOUTT;  R = DLAT;   C = DMODEL; break;
    }
    int bx = blockIdx.x * 32, by = blockIdx.y * 32;
    if (bx >= C || by >= R) return;
    __shared__ float t[32][33];
    int x = threadIdx.x, y = threadIdx.y;
#pragma unroll
    for (int j = 0; j < 32; j += 8)
        t[y + j][x] = S[(long)(by + y + j) * C + bx + x];
    __syncthreads();
#pragma unroll
    for (int j = 0; j < 32; j += 8)
        D[(long)(bx + y + j) * R + by + x] = t[x][y + j];
}

// ---------------------------------------------------------------------------
// Flash attention for d_h = 64 (stages 2 and 3)
// ---------------------------------------------------------------------------
#define ALD 68

__global__ __launch_bounds__(256) void attn64(
    const float* __restrict__ Q, long qBatch,
    const float* __restrict__ Kp, const float* __restrict__ Vp, long kvBatch,
    int nkeys, float* __restrict__ Out, long oBatch)
{
    extern __shared__ float smf[];
    float* Qs = smf;
    float* Ks = Qs + 64 * ALD;
    float* Vs = Ks + 64 * ALD;
    float* Ps = Vs + 64 * ALD;
    float* mrow = Ps + 64 * ALD;
    float* lrow = mrow + 64;
    float* crow = lrow + 64;

    int tid = threadIdx.x;
    int h = blockIdx.y, b = blockIdx.z;
    int qtile = blockIdx.x;
    const float scale = 0.125f;

    const float* Qbase = Q + (long)b * qBatch + (long)qtile * 64 * DLAT + h * DHEAD;
    const float* Kbase = Kp + (long)b * kvBatch + h * DHEAD;
    const float* Vbase = Vp + (long)b * kvBatch + h * DHEAD;

#pragma unroll
    for (int i = 0; i < 16; i++) {
        int idx = tid + 256 * i;
        int q = idx >> 6, d = idx & 63;
        Qs[d * ALD + q] = Qbase[(long)q * DLAT + d] * scale;
    }
    if (tid < 64) { mrow[tid] = -1e30f; lrow[tid] = 0.0f; }
    __syncthreads();

    int tx = tid & 15, ty = tid >> 4;
    float o[4][4];
#pragma unroll
    for (int i = 0; i < 4; i++)
#pragma unroll
        for (int j = 0; j < 4; j++) o[i][j] = 0.0f;

    for (int k0 = 0; k0 < nkeys; k0 += 64) {
#pragma unroll
        for (int i = 0; i < 16; i++) {
            int idx = tid + 256 * i;
            int k = idx >> 6, d = idx & 63;
            float kv = Kbase[(long)(k0 + k) * DLAT + d];
            float vv = Vbase[(long)(k0 + k) * DLAT + d];
            Ks[d * ALD + k] = kv;
            Vs[k * ALD + d] = vv;
        }
        __syncthreads();

        float s[4][4];
#pragma unroll
        for (int i = 0; i < 4; i++)
#pragma unroll
            for (int j = 0; j < 4; j++) s[i][j] = 0.0f;
#pragma unroll
        for (int d = 0; d < 64; d++) {
            float4 qf = *(float4*)&Qs[d * ALD + ty * 4];
            float4 kf = *(float4*)&Ks[d * ALD + tx * 4];
            float qa[4] = {qf.x, qf.y, qf.z, qf.w};
            float ka[4] = {kf.x, kf.y, kf.z, kf.w};
#pragma unroll
            for (int ki = 0; ki < 4; ki++)
#pragma unroll
                for (int qj = 0; qj < 4; qj++)
                    s[ki][qj] += ka[ki] * qa[qj];
        }
#pragma unroll
        for (int ki = 0; ki < 4; ki++)
            *(float4*)&Ps[(tx * 4 + ki) * ALD + ty * 4] =
                make_float4(s[ki][0], s[ki][1], s[ki][2], s[ki][3]);
        __syncthreads();

        if (tid < 64) {
            int q = tid;
            float mold = mrow[q];
            float mx = mold;
            for (int k = 0; k < 64; k++) mx = fmaxf(mx, Ps[k * ALD + q]);
            float c = __expf(mold - mx);
            float l = lrow[q] * c;
            for (int k = 0; k < 64; k++) {
                float p = __expf(Ps[k * ALD + q] - mx);
                Ps[k * ALD + q] = p;
                l += p;
            }
            mrow[q] = mx; lrow[q] = l; crow[q] = c;
        }
        __syncthreads();

        float cq[4];
        *(float4*)cq = *(float4*)&crow[ty * 4];
#pragma unroll
        for (int i = 0; i < 4; i++)
#pragma unroll
            for (int j = 0; j < 4; j++) o[i][j] *= cq[i];

#pragma unroll 8
        for (int j = 0; j < 64; j++) {
            float4 pf = *(float4*)&Ps[j * ALD + ty * 4];
            float4 vf = *(float4*)&Vs[j * ALD + tx * 4];
            float pa[4] = {pf.x, pf.y, pf.z, pf.w};
            float va[4] = {vf.x, vf.y, vf.z, vf.w};
#pragma unroll
            for (int qi = 0; qi < 4; qi++)
#pragma unroll
                for (int dj = 0; dj < 4; dj++)
                    o[qi][dj] += pa[qi] * va[dj];
        }
        __syncthreads();
    }

    float lq[4];
    *(float4*)lq = *(float4*)&lrow[ty * 4];
    float* Obase = Out + (long)b * oBatch + (long)qtile * 64 * DLAT + h * DHEAD;
#pragma unroll
    for (int qi = 0; qi < 4; qi++) {
        float inv = 1.0f / lq[qi];
        int q = ty * 4 + qi;
        float* op = Obase + (long)q * DLAT + tx * 4;
        *(float4*)op = make_float4(o[qi][0] * inv, o[qi][1] * inv,
                                   o[qi][2] * inv, o[qi][3] * inv);
    }
}

// ---------------------------------------------------------------------------
// Stage-1 split-K attention: grid (SPLITS, NHEADS, BATCH).
// ---------------------------------------------------------------------------
__global__ __launch_bounds__(256) void attn1_split(
    const float* __restrict__ Q,       // gQ1 [64, 1024], shared across batch
    const float* __restrict__ Kp, const float* __restrict__ Vp,
    float* __restrict__ po, float* __restrict__ pm, float* __restrict__ pl)
{
    extern __shared__ float smf[];
    float* Qs = smf;
    float* Ks = Qs + 64 * ALD;
    float* Vs = Ks + 64 * ALD;
    float* Ps = Vs + 64 * ALD;
    float* mrow = Ps + 64 * ALD;
    float* lrow = mrow + 64;
    float* crow = lrow + 64;

    int tid = threadIdx.x;
    int s = blockIdx.x, h = blockIdx.y, b = blockIdx.z;
    const float scale = 0.125f;

    const float* Qbase = Q + h * DHEAD;
    const float* Kbase = Kp + (long)b * TSEQ * DLAT + h * DHEAD;
    const float* Vbase = Vp + (long)b * TSEQ * DLAT + h * DHEAD;
    const int key0 = s * (TSEQ / SPLITS);

#pragma unroll
    for (int i = 0; i < 16; i++) {
        int idx = tid + 256 * i;
        int q = idx >> 6, d = idx & 63;
        Qs[d * ALD + q] = Qbase[(long)q * DLAT + d] * scale;
    }
    if (tid < 64) { mrow[tid] = -1e30f; lrow[tid] = 0.0f; }
    __syncthreads();

    int tx = tid & 15, ty = tid >> 4;
    float o[4][4];
#pragma unroll
    for (int i = 0; i < 4; i++)
#pragma unroll
        for (int j = 0; j < 4; j++) o[i][j] = 0.0f;

    for (int kc = 0; kc < TSEQ / SPLITS; kc += 64) {
        int k0 = key0 + kc;
#pragma unroll
        for (int i = 0; i < 16; i++) {
            int idx = tid + 256 * i;
            int k = idx >> 6, d = idx & 63;
            Ks[d * ALD + k] = Kbase[(long)(k0 + k) * DLAT + d];
            Vs[k * ALD + d] = Vbase[(long)(k0 + k) * DLAT + d];
        }
        __syncthreads();

        float sacc[4][4];
#pragma unroll
        for (int i = 0; i < 4; i++)
#pragma unroll
            for (int j = 0; j < 4; j++) sacc[i][j] = 0.0f;
#pragma unroll
        for (int d = 0; d < 64; d++) {
            float4 qf = *(float4*)&Qs[d * ALD + ty * 4];
            float4 kf = *(float4*)&Ks[d * ALD + tx * 4];
            float qa[4] = {qf.x, qf.y, qf.z, qf.w};
            float ka[4] = {kf.x, kf.y, kf.z, kf.w};
#pragma unroll
            for (int ki = 0; ki < 4; ki++)
#pragma unroll
                for (int qj = 0; qj < 4; qj++)
                    sacc[ki][qj] += ka[ki] * qa[qj];
        }
#pragma unroll
        for (int ki = 0; ki < 4; ki++)
            *(float4*)&Ps[(tx * 4 + ki) * ALD + ty * 4] =
                make_float4(sacc[ki][0], sacc[ki][1], sacc[ki][2], sacc[ki][3]);
        __syncthreads();

        if (tid < 64) {
            int q = tid;
            float mold = mrow[q];
            float mx = mold;
            for (int k = 0; k < 64; k++) mx = fmaxf(mx, Ps[k * ALD + q]);
            float c = __expf(mold - mx);
            float l = lrow[q] * c;
            for (int k = 0; k < 64; k++) {
                float p = __expf(Ps[k * ALD + q] - mx);
                Ps[k * ALD + q] = p;
                l += p;
            }
            mrow[q] = mx; lrow[q] = l; crow[q] = c;
        }
        __syncthreads();

        float cq[4];
        *(float4*)cq = *(float4*)&crow[ty * 4];
#pragma unroll
        for (int i = 0; i < 4; i++)
#pragma unroll
            for (int j = 0; j < 4; j++) o[i][j] *= cq[i];

#pragma unroll 8
        for (int j = 0; j < 64; j++) {
            float4 pf = *(float4*)&Ps[j * ALD + ty * 4];
            float4 vf = *(float4*)&Vs[j * ALD + tx * 4];
            float pa[4] = {pf.x, pf.y, pf.z, pf.w};
            float va[4] = {vf.x, vf.y, vf.z, vf.w};
#pragma unroll
            for (int qi = 0; qi < 4; qi++)
#pragma unroll
                for (int dj = 0; dj < 4; dj++)
                    o[qi][dj] += pa[qi] * va[dj];
        }
        __syncthreads();
    }

    // Write unnormalized partials
    long base = ((((long)s * BATCH + b) * NHEADS + h) * 64);
    float* pob = po + base * 64;
#pragma unroll
    for (int qi = 0; qi < 4; qi++) {
        int q = ty * 4 + qi;
        *(float4*)(pob + (long)q * 64 + tx * 4) =
            make_float4(o[qi][0], o[qi][1], o[qi][2], o[qi][3]);
    }
    if (tid < 64) {
        pm[base + tid] = mrow[tid];
        pl[base + tid] = lrow[tid];
    }
}

// ---------------------------------------------------------------------------
// Combine stage-1 partials -> z[b][q][h*64+d]. grid (NHEADS, BATCH).
// ---------------------------------------------------------------------------
__global__ __launch_bounds__(256) void combine1(
    const float* __restrict__ po, const float* __restrict__ pm,
    const float* __restrict__ pl, float* __restrict__ z)
{
    __shared__ float coef[SPLITS][64];
    int tid = threadIdx.x;
    int h = blockIdx.x, b = blockIdx.y;

    if (tid < 64) {
        int q = tid;
        float mx = -1e30f;
        float ms[SPLITS];
#pragma unroll
        for (int s = 0; s < SPLITS; s++) {
            ms[s] = pm[((((long)s * BATCH + b) * NHEADS + h) * 64) + q];
            mx = fmaxf(mx, ms[s]);
        }
        float lsum = 0.0f;
        float es[SPLITS];
#pragma unroll
        for (int s = 0; s < SPLITS; s++) {
            es[s] = __expf(ms[s] - mx);
            lsum += es[s] * pl[((((long)s * BATCH + b) * NHEADS + h) * 64) + q];
        }
        float inv = 1.0f / lsum;
#pragma unroll
        for (int s = 0; s < SPLITS; s++) coef[s][q] = es[s] * inv;
    }
    __syncthreads();

#pragma unroll
    for (int i = 0; i < 16; i++) {
        int idx = tid + 256 * i;       // 0..4095
        int q = idx >> 6, d = idx & 63;
        float sum = 0.0f;
#pragma unroll
        for (int s = 0; s < SPLITS; s++) {
            sum += coef[s][q] *
                   po[(((((long)s * BATCH + b) * NHEADS + h) * 64) + q) * 64 + d];
        }
        z[(long)b * NLAT * DLAT + (long)q * DLAT + h * DHEAD + d] = sum;
    }
}

// ---------------------------------------------------------------------------
// Host launch
// ---------------------------------------------------------------------------
static void launch_gemm_mma(const float* A, const float* Bt, float* C,
                            int M, int N, int K)
{
    dim3 grid(N / GBN, (M + GBM - 1) / GBM);
    gemm_mma<<<grid, 128, GEMM_SMEM>>>(A, Bt, C, M, N, K);
}

extern "C" void kernel_launch(void* const* d_in, const int* in_sizes, int n_in,
                              void* d_out, int out_size)
{
    const float* x       = (const float*)d_in[0];
    const float* L       = (const float*)d_in[1];
    const float* W_q_lat = (const float*)d_in[2];
    const float* W_k_in  = (const float*)d_in[3];
    const float* W_v_in  = (const float*)d_in[4];
    const float* W_q_in  = (const float*)d_in[5];
    const float* W_k_lat = (const float*)d_in[6];
    const float* W_v_lat = (const float*)d_in[7];
    const float* W_out   = (const float*)d_in[8];
    float* out = (float*)d_out;

    float* scratch = nullptr;
    cudaGetSymbolAddress((void**)&scratch, g_scratch);

    float* gK    = scratch + OFF_K;
    float* gV    = scratch + OFF_V;
    float* gQx   = scratch + OFF_QX;
    float* gXlat = scratch + OFF_XLAT;
    float* gQ1   = scratch + OFF_Q1;
    float* gZ    = scratch + OFF_Z;
    float* gZ2   = scratch + OFF_Z2;
    float* gQl   = scratch + OFF_QL;
    float* gKl   = scratch + OFF_KL;
    float* gVl   = scratch + OFF_VL;
    float* gKz   = scratch + OFF_KZ;
    float* gVz   = scratch + OFF_VZ;
    float* gPo   = scratch + OFF_PO;
    float* gPm   = scratch + OFF_PM;
    float* gPl   = scratch + OFF_PL;

    float* tWkin  = scratch + OFF_WKINT;
    float* tWvin  = scratch + OFF_WVINT;
    float* tWqin  = scratch + OFF_WQINT;
    float* tWqlat = scratch + OFF_WQLATT;
    float* tWklat = scratch + OFF_WKLATT;
    float* tWvlat = scratch + OFF_WVLATT;
    float* tWout  = scratch + OFF_WOUTT;

    const int ATTN_SMEM = (4 * 64 * ALD + 192) * 4;   // 70400 B
    cudaFuncSetAttribute(attn64, cudaFuncAttributeMaxDynamicSharedMemorySize,
                         ATTN_SMEM);
    cudaFuncSetAttribute(attn1_split, cudaFuncAttributeMaxDynamicSharedMemorySize,
                         ATTN_SMEM);
    cudaFuncSetAttribute(gemm_mma, cudaFuncAttributeMaxDynamicSharedMemorySize,
                         GEMM_SMEM);

    // (1) all transposes in one launch
    transp_all<<<dim3(64, 64, 7), dim3(32, 8)>>>(
        W_q_lat, W_k_in, W_v_in, W_q_in, W_k_lat, W_v_lat, W_out, scratch);

    // (2) q1  (3) K  (4) V  (5)(6) Qx in two halves -> launch #6 is a big gemm
    launch_gemm_mma(L, tWqlat, gQ1, NLAT, DLAT, DLAT);
    launch_gemm_mma(x, tWkin, gK, BT, DLAT, DMODEL);
    launch_gemm_mma(x, tWvin, gV, BT, DLAT, DMODEL);
    launch_gemm_mma(x, tWqin, gQx, BT / 2, DLAT, DMODEL);
    launch_gemm_mma(x + (long)(BT / 2) * DMODEL, tWqin,
                    gQx + (long)(BT / 2) * DLAT, BT / 2, DLAT, DMODEL);

    // Stage 1: split-K attention + combine
    attn1_split<<<dim3(SPLITS, NHEADS, BATCH), 256, ATTN_SMEM>>>(
        gQ1, gK, gV, gPo, gPm, gPl);
    combine1<<<dim3(NHEADS, BATCH), 256>>>(gPo, gPm, gPl, gZ);

    // Stage 2 projections
    launch_gemm_mma(gZ, tWqlat, gQl, BATCH * NLAT, DLAT, DLAT);
    launch_gemm_mma(gZ, tWklat, gKl, BATCH * NLAT, DLAT, DLAT);
    launch_gemm_mma(gZ, tWvlat, gVl, BATCH * NLAT, DLAT, DLAT);

    // Stage 2: latent self-attention
    {
        dim3 grid(1, NHEADS, BATCH);
        attn64<<<grid, 256, ATTN_SMEM>>>(gQl, (long)NLAT * DLAT, gKl, gVl,
                                         (long)NLAT * DLAT, NLAT,
                                         gZ2, (long)NLAT * DLAT);
    }

    // Stage 3 projections
    launch_gemm_mma(gZ2, tWklat, gKz, BATCH * NLAT, DLAT, DLAT);
    launch_gemm_mma(gZ2, tWvlat, gVz, BATCH * NLAT, DLAT, DLAT);

    // Stage 3: tokens attend to latents
    {
        dim3 grid(TSEQ / 64, NHEADS, BATCH);
        attn64<<<grid, 256, ATTN_SMEM>>>(gQx, (long)TSEQ * DLAT, gKz, gVz,
                                         (long)NLAT * DLAT, NLAT,
                                         gXlat, (long)TSEQ * DLAT);
    }

    // Output projection
    launch_gemm_mma(gXlat, tWout, out, BT, DMODEL, DLAT);
}

// round 14
// speedup vs baseline: 3.4647x; 1.1450x over previous
#include <cuda_runtime.h>
#include <cuda_bf16.h>
#include <cstdint>

// Problem constants
#define BATCH 4
#define TSEQ 4096
#define DMODEL 2048
#define NLAT 64
#define DLAT 1024
#define NHEADS 16
#define DHEAD 64
#define BT (BATCH * TSEQ)        // 16384
#define SPLITS 16

// ---------------------------------------------------------------------------
// Scratch offsets (floats)
// ---------------------------------------------------------------------------
#define OFF_K      0L
#define OFF_V      16777216L
#define OFF_QX     33554432L
#define OFF_XLAT   50331648L
#define OFF_Q1     67108864L
#define OFF_Z      67174400L
#define OFF_Z2     67436544L
#define OFF_QL     67698688L
#define OFF_KL     67960832L
#define OFF_VL     68222976L
#define OFF_KZ     68485120L
#define OFF_VZ     68747264L
// transposed (and tf32-rounded) weights [N,K]
#define OFF_WKINT  69009408L
#define OFF_WVINT  71106560L
#define OFF_WQINT  73203712L
#define OFF_WQLATT 75300864L
#define OFF_WKLATT 76349440L
#define OFF_WVLATT 77398016L
#define OFF_WOUTT  78446592L
// stage-1 split-K partials
#define OFF_PO     80543744L
#define OFF_PM     84738048L
#define OFF_PL     84803584L
// tf32-rounded copies of inputs
#define OFF_XTF    84869120L     // [BT, DMODEL]
#define OFF_LTF    118423552L    // [64, 1024]
#define SCRATCH_FLOATS 118489088L

__device__ float g_scratch[SCRATCH_FLOATS];

__device__ __forceinline__ uint32_t tf32r(float x) {
    uint32_t r;
    asm("cvt.rna.tf32.f32 %0, %1;" : "=r"(r) : "f"(x));
    return r;
}
__device__ __forceinline__ float tf32f(float x) {
    return __uint_as_float(tf32r(x));
}
__device__ __forceinline__ uint32_t smem_u32(const void* p) {
    uint32_t a;
    asm("{ .reg .u64 t; cvta.to.shared.u64 t, %1; cvt.u32.u64 %0, t; }"
        : "=r"(a) : "l"(p));
    return a;
}

// ---------------------------------------------------------------------------
// Round a float buffer to tf32 (float4 granularity; n % 1024 == 0).
// ---------------------------------------------------------------------------
__global__ void round_tf32(const float* __restrict__ src, float* __restrict__ dst,
                           long n4)
{
    long i = (long)blockIdx.x * blockDim.x + threadIdx.x;
    if (i < n4) {
        float4 v = ((const float4*)src)[i];
        v.x = tf32f(v.x); v.y = tf32f(v.y); v.z = tf32f(v.z); v.w = tf32f(v.w);
        ((float4*)dst)[i] = v;
    }
}

// ---------------------------------------------------------------------------
// tf32 mma.sync GEMM with cp.async 3-stage pipeline.
// C[M,N] = A[M,K] * Bt[N,K]^T. A and Bt must already be tf32-valued.
// CTA tile 128x128, BK=16, 128 threads (2x2 warps), warp tile 64x64.
// ---------------------------------------------------------------------------
#define GBM 128
#define GBN 128
#define GBK 16
#define LDSA 20
#define BUF_FLOATS (GBM * LDSA)                 // 2560 floats per array
#define STAGE_BYTES (2 * BUF_FLOATS * 4)        // 20480 (A + B)
#define GSTAGES 3
#define GEMM_SMEM (GSTAGES * STAGE_BYTES)       // 61440

__global__ __launch_bounds__(128, 2) void gemm_mma(
    const float* __restrict__ A, const float* __restrict__ Bt,
    float* __restrict__ C, int M, int N, int K)
{
    extern __shared__ float sm[];
    const uint32_t smb = smem_u32(sm);
    const int tid = threadIdx.x;
    const int wid = tid >> 5, lane = tid & 31;
    const int grp = lane >> 2, qc = lane & 3;
    const int warp_m = wid & 1, warp_n = wid >> 1;
    const int row0 = blockIdx.y * GBM;
    const int col0 = blockIdx.x * GBN;
    const int nchunks = K / GBK;

    // Per-thread cp.async mapping: 4 A rows + 4 B rows, 16B each.
    const int rbase = tid >> 2;
    const int cc = (tid & 3) * 4;
    const float* asrc[4];
    const float* bsrc[4];
    uint32_t adst[4], bdst[4];
    int asz[4];
#pragma unroll
    for (int i = 0; i < 4; i++) {
        int r = rbase + 32 * i;
        asrc[i] = A + (long)(row0 + r) * K + cc;
        bsrc[i] = Bt + (long)(col0 + r) * K + cc;
        adst[i] = smb + (uint32_t)(r * LDSA + cc) * 4;
        bdst[i] = smb + (uint32_t)(BUF_FLOATS + r * LDSA + cc) * 4;
        asz[i] = (row0 + r < M) ? 16 : 0;
    }

#define GISSUE(c, s) do { \
    uint32_t _so = (uint32_t)(s) * STAGE_BYTES; \
    long _go = (long)(c) * GBK; \
    _Pragma("unroll") \
    for (int _i = 0; _i < 4; _i++) { \
        asm volatile("cp.async.cg.shared.global [%0], [%1], 16, %2;" \
            :: "r"(adst[_i] + _so), "l"(asrc[_i] + _go), "r"(asz[_i])); \
        asm volatile("cp.async.cg.shared.global [%0], [%1], 16;" \
            :: "r"(bdst[_i] + _so), "l"(bsrc[_i] + _go)); \
    } \
    asm volatile("cp.async.commit_group;"); \
} while (0)

    float acc[4][8][4];
#pragma unroll
    for (int i = 0; i < 4; i++)
#pragma unroll
        for (int j = 0; j < 8; j++)
#pragma unroll
            for (int l = 0; l < 4; l++) acc[i][j][l] = 0.0f;

    // Prologue: stages 0, 1
    GISSUE(0, 0);
    GISSUE(1, 1);

    for (int c = 0; c < nchunks; c++) {
        if (c + 1 < nchunks)
            asm volatile("cp.async.wait_group 1;");
        else
            asm volatile("cp.async.wait_group 0;");
        __syncthreads();

        int cn = c + GSTAGES - 1;
        if (cn < nchunks) GISSUE(cn, cn % GSTAGES);

        float* As = sm + (c % GSTAGES) * (2 * BUF_FLOATS);
        float* Bs = As + BUF_FLOATS;

#pragma unroll
        for (int ks = 0; ks < 2; ks++) {
            int k0 = ks * 8;
            uint32_t a[4][4], b[8][2];
#pragma unroll
            for (int mt = 0; mt < 4; mt++) {
                int r = warp_m * 64 + mt * 16 + grp;
                const uint32_t* p0 = (const uint32_t*)(As + r * LDSA + k0 + qc);
                const uint32_t* p1 = (const uint32_t*)(As + (r + 8) * LDSA + k0 + qc);
                a[mt][0] = p0[0]; a[mt][2] = p0[4];
                a[mt][1] = p1[0]; a[mt][3] = p1[4];
            }
#pragma unroll
            for (int nt = 0; nt < 8; nt++) {
                int r = warp_n * 64 + nt * 8 + grp;
                const uint32_t* p = (const uint32_t*)(Bs + r * LDSA + k0 + qc);
                b[nt][0] = p[0]; b[nt][1] = p[4];
            }
#pragma unroll
            for (int mt = 0; mt < 4; mt++)
#pragma unroll
                for (int nt = 0; nt < 8; nt++)
                    asm volatile(
                        "mma.sync.aligned.m16n8k8.row.col.f32.tf32.tf32.f32 "
                        "{%0,%1,%2,%3}, {%4,%5,%6,%7}, {%8,%9}, {%0,%1,%2,%3};"
                        : "+f"(acc[mt][nt][0]), "+f"(acc[mt][nt][1]),
                          "+f"(acc[mt][nt][2]), "+f"(acc[mt][nt][3])
                        : "r"(a[mt][0]), "r"(a[mt][1]), "r"(a[mt][2]), "r"(a[mt][3]),
                          "r"(b[nt][0]), "r"(b[nt][1]));
        }
        __syncthreads();
    }

    // Epilogue
#pragma unroll
    for (int mt = 0; mt < 4; mt++) {
        int r = row0 + warp_m * 64 + mt * 16 + grp;
#pragma unroll
        for (int nt = 0; nt < 8; nt++) {
            int col = col0 + warp_n * 64 + nt * 8 + qc * 2;
            if (r < M)
                *(float2*)(C + (long)r * N + col) =
                    make_float2(acc[mt][nt][0], acc[mt][nt][1]);
            if (r + 8 < M)
                *(float2*)(C + (long)(r + 8) * N + col) =
                    make_float2(acc[mt][nt][2], acc[mt][nt][3]);
        }
    }
#undef GISSUE
}

// ---------------------------------------------------------------------------
// Batched transpose of all 7 weights, tf32-rounded at store.
// ---------------------------------------------------------------------------
__global__ void transp_all(
    const float* __restrict__ W_q_lat, const float* __restrict__ W_k_in,
    const float* __restrict__ W_v_in,  const float* __restrict__ W_q_in,
    const float* __restrict__ W_k_lat, const float* __restrict__ W_v_lat,
    const float* __restrict__ W_out,   float* __restrict__ scr)
{
    const float* S; float* D; int R, C;
    switch (blockIdx.z) {
        case 0: S = W_k_in;  D = scr + OFF_WKINT;  R = DMODEL; C = DLAT;   break;
        case 1: S = W_v_in;  D = scr + OFF_WVINT;  R = DMODEL; C = DLAT;   break;
        case 2: S = W_q_in;  D = scr + OFF_WQINT;  R = DMODEL; C = DLAT;   break;
        case 3: S = W_q_lat; D = scr + OFF_WQLATT; R = DLAT;   C = DLAT;   break;
        case 4: S = W_k_lat; D = scr + OFF_WKLATT; R = DLAT;   C = DLAT;   break;
        case 5: S = W_v_lat; D = scr + OFF_WVLATT; R = DLAT;   C = DLAT;   break;
        default: S = W_out;  D = scr + OFF_WOUTT;  R = DLAT;   C = DMODEL; break;
    }
    int bx = blockIdx.x * 32, by = blockIdx.y * 32;
    if (bx >= C || by >= R) return;
    __shared__ float t[32][33];
    int x = threadIdx.x, y = threadIdx.y;
#pragma unroll
    for (int j = 0; j < 32; j += 8)
        t[y + j][x] = S[(long)(by + y + j) * C + bx + x];
    __syncthreads();
#pragma unroll
    for (int j = 0; j < 32; j += 8)
        D[(long)(bx + y + j) * R + by + x] = tf32f(t[x][y + j]);
}

// ---------------------------------------------------------------------------
// Flash attention for d_h = 64 (stages 2 and 3); output tf32-rounded
// (outputs feed later GEMMs as A operands).
// ---------------------------------------------------------------------------
#define ALD 68

__global__ __launch_bounds__(256) void attn64(
    const float* __restrict__ Q, long qBatch,
    const float* __restrict__ Kp, const float* __restrict__ Vp, long kvBatch,
    int nkeys, float* __restrict__ Out, long oBatch)
{
    extern __shared__ float smf[];
    float* Qs = smf;
    float* Ks = Qs + 64 * ALD;
    float* Vs = Ks + 64 * ALD;
    float* Ps = Vs + 64 * ALD;
    float* mrow = Ps + 64 * ALD;
    float* lrow = mrow + 64;
    float* crow = lrow + 64;

    int tid = threadIdx.x;
    int h = blockIdx.y, b = blockIdx.z;
    int qtile = blockIdx.x;
    const float scale = 0.125f;

    const float* Qbase = Q + (long)b * qBatch + (long)qtile * 64 * DLAT + h * DHEAD;
    const float* Kbase = Kp + (long)b * kvBatch + h * DHEAD;
    const float* Vbase = Vp + (long)b * kvBatch + h * DHEAD;

#pragma unroll
    for (int i = 0; i < 16; i++) {
        int idx = tid + 256 * i;
        int q = idx >> 6, d = idx & 63;
        Qs[d * ALD + q] = Qbase[(long)q * DLAT + d] * scale;
    }
    if (tid < 64) { mrow[tid] = -1e30f; lrow[tid] = 0.0f; }
    __syncthreads();

    int tx = tid & 15, ty = tid >> 4;
    float o[4][4];
#pragma unroll
    for (int i = 0; i < 4; i++)
#pragma unroll
        for (int j = 0; j < 4; j++) o[i][j] = 0.0f;

    for (int k0 = 0; k0 < nkeys; k0 += 64) {
#pragma unroll
        for (int i = 0; i < 16; i++) {
            int idx = tid + 256 * i;
            int k = idx >> 6, d = idx & 63;
            float kv = Kbase[(long)(k0 + k) * DLAT + d];
            float vv = Vbase[(long)(k0 + k) * DLAT + d];
            Ks[d * ALD + k] = kv;
            Vs[k * ALD + d] = vv;
        }
        __syncthreads();

        float s[4][4];
#pragma unroll
        for (int i = 0; i < 4; i++)
#pragma unroll
            for (int j = 0; j < 4; j++) s[i][j] = 0.0f;
#pragma unroll
        for (int d = 0; d < 64; d++) {
            float4 qf = *(float4*)&Qs[d * ALD + ty * 4];
            float4 kf = *(float4*)&Ks[d * ALD + tx * 4];
            float qa[4] = {qf.x, qf.y, qf.z, qf.w};
            float ka[4] = {kf.x, kf.y, kf.z, kf.w};
#pragma unroll
            for (int ki = 0; ki < 4; ki++)
#pragma unroll
                for (int qj = 0; qj < 4; qj++)
                    s[ki][qj] += ka[ki] * qa[qj];
        }
#pragma unroll
        for (int ki = 0; ki < 4; ki++)
            *(float4*)&Ps[(tx * 4 + ki) * ALD + ty * 4] =
                make_float4(s[ki][0], s[ki][1], s[ki][2], s[ki][3]);
        __syncthreads();

        if (tid < 64) {
            int q = tid;
            float mold = mrow[q];
            float mx = mold;
            for (int k = 0; k < 64; k++) mx = fmaxf(mx, Ps[k * ALD + q]);
            float c = __expf(mold - mx);
            float l = lrow[q] * c;
            for (int k = 0; k < 64; k++) {
                float p = __expf(Ps[k * ALD + q] - mx);
                Ps[k * ALD + q] = p;
                l += p;
            }
            mrow[q] = mx; lrow[q] = l; crow[q] = c;
        }
        __syncthreads();

        float cq[4];
        *(float4*)cq = *(float4*)&crow[ty * 4];
#pragma unroll
        for (int i = 0; i < 4; i++)
#pragma unroll
            for (int j = 0; j < 4; j++) o[i][j] *= cq[i];

#pragma unroll 8
        for (int j = 0; j < 64; j++) {
            float4 pf = *(float4*)&Ps[j * ALD + ty * 4];
            float4 vf = *(float4*)&Vs[j * ALD + tx * 4];
            float pa[4] = {pf.x, pf.y, pf.z, pf.w};
            float va[4] = {vf.x, vf.y, vf.z, vf.w};
#pragma unroll
            for (int qi = 0; qi < 4; qi++)
#pragma unroll
                for (int dj = 0; dj < 4; dj++)
                    o[qi][dj] += pa[qi] * va[dj];
        }
        __syncthreads();
    }

    float lq[4];
    *(float4*)lq = *(float4*)&lrow[ty * 4];
    float* Obase = Out + (long)b * oBatch + (long)qtile * 64 * DLAT + h * DHEAD;
#pragma unroll
    for (int qi = 0; qi < 4; qi++) {
        float inv = 1.0f / lq[qi];
        int q = ty * 4 + qi;
        float* op = Obase + (long)q * DLAT + tx * 4;
        *(float4*)op = make_float4(tf32f(o[qi][0] * inv), tf32f(o[qi][1] * inv),
                                   tf32f(o[qi][2] * inv), tf32f(o[qi][3] * inv));
    }
}

// ---------------------------------------------------------------------------
// Stage-1 split-K attention: grid (SPLITS, NHEADS, BATCH).
// ---------------------------------------------------------------------------
__global__ __launch_bounds__(256) void attn1_split(
    const float* __restrict__ Q,
    const float* __restrict__ Kp, const float* __restrict__ Vp,
    float* __restrict__ po, float* __restrict__ pm, float* __restrict__ pl)
{
    extern __shared__ float smf[];
    float* Qs = smf;
    float* Ks = Qs + 64 * ALD;
    float* Vs = Ks + 64 * ALD;
    float* Ps = Vs + 64 * ALD;
    float* mrow = Ps + 64 * ALD;
    float* lrow = mrow + 64;
    float* crow = lrow + 64;

    int tid = threadIdx.x;
    int s = blockIdx.x, h = blockIdx.y, b = blockIdx.z;
    const float scale = 0.125f;

    const float* Qbase = Q + h * DHEAD;
    const float* Kbase = Kp + (long)b * TSEQ * DLAT + h * DHEAD;
    const float* Vbase = Vp + (long)b * TSEQ * DLAT + h * DHEAD;
    const int key0 = s * (TSEQ / SPLITS);

#pragma unroll
    for (int i = 0; i < 16; i++) {
        int idx = tid + 256 * i;
        int q = idx >> 6, d = idx & 63;
        Qs[d * ALD + q] = Qbase[(long)q * DLAT + d] * scale;
    }
    if (tid < 64) { mrow[tid] = -1e30f; lrow[tid] = 0.0f; }
    __syncthreads();

    int tx = tid & 15, ty = tid >> 4;
    float o[4][4];
#pragma unroll
    for (int i = 0; i < 4; i++)
#pragma unroll
        for (int j = 0; j < 4; j++) o[i][j] = 0.0f;

    for (int kc = 0; kc < TSEQ / SPLITS; kc += 64) {
        int k0 = key0 + kc;
#pragma unroll
        for (int i = 0; i < 16; i++) {
            int idx = tid + 256 * i;
            int k = idx >> 6, d = idx & 63;
            Ks[d * ALD + k] = Kbase[(long)(k0 + k) * DLAT + d];
            Vs[k * ALD + d] = Vbase[(long)(k0 + k) * DLAT + d];
        }
        __syncthreads();

        float sacc[4][4];
#pragma unroll
        for (int i = 0; i < 4; i++)
#pragma unroll
            for (int j = 0; j < 4; j++) sacc[i][j] = 0.0f;
#pragma unroll
        for (int d = 0; d < 64; d++) {
            float4 qf = *(float4*)&Qs[d * ALD + ty * 4];
            float4 kf = *(float4*)&Ks[d * ALD + tx * 4];
            float qa[4] = {qf.x, qf.y, qf.z, qf.w};
            float ka[4] = {kf.x, kf.y, kf.z, kf.w};
#pragma unroll
            for (int ki = 0; ki < 4; ki++)
#pragma unroll
                for (int qj = 0; qj < 4; qj++)
                    sacc[ki][qj] += ka[ki] * qa[qj];
        }
#pragma unroll
        for (int ki = 0; ki < 4; ki++)
            *(float4*)&Ps[(tx * 4 + ki) * ALD + ty * 4] =
                make_float4(sacc[ki][0], sacc[ki][1], sacc[ki][2], sacc[ki][3]);
        __syncthreads();

        if (tid < 64) {
            int q = tid;
            float mold = mrow[q];
            float mx = mold;
            for (int k = 0; k < 64; k++) mx = fmaxf(mx, Ps[k * ALD + q]);
            float c = __expf(mold - mx);
            float l = lrow[q] * c;
            for (int k = 0; k < 64; k++) {
                float p = __expf(Ps[k * ALD + q] - mx);
                Ps[k * ALD + q] = p;
                l += p;
            }
            mrow[q] = mx; lrow[q] = l; crow[q] = c;
        }
        __syncthreads();

        float cq[4];
        *(float4*)cq = *(float4*)&crow[ty * 4];
#pragma unroll
        for (int i = 0; i < 4; i++)
#pragma unroll
            for (int j = 0; j < 4; j++) o[i][j] *= cq[i];

#pragma unroll 8
        for (int j = 0; j < 64; j++) {
            float4 pf = *(float4*)&Ps[j * ALD + ty * 4];
            float4 vf = *(float4*)&Vs[j * ALD + tx * 4];
            float pa[4] = {pf.x, pf.y, pf.z, pf.w};
            float va[4] = {vf.x, vf.y, vf.z, vf.w};
#pragma unroll
            for (int qi = 0; qi < 4; qi++)
#pragma unroll
                for (int dj = 0; dj < 4; dj++)
                    o[qi][dj] += pa[qi] * va[dj];
        }
        __syncthreads();
    }

    long base = ((((long)s * BATCH + b) * NHEADS + h) * 64);
    float* pob = po + base * 64;
#pragma unroll
    for (int qi = 0; qi < 4; qi++) {
        int q = ty * 4 + qi;
        *(float4*)(pob + (long)q * 64 + tx * 4) =
            make_float4(o[qi][0], o[qi][1], o[qi][2], o[qi][3]);
    }
    if (tid < 64) {
        pm[base + tid] = mrow[tid];
        pl[base + tid] = lrow[tid];
    }
}

// ---------------------------------------------------------------------------
// Combine stage-1 partials -> z (tf32-rounded; z feeds GEMMs as A).
// ---------------------------------------------------------------------------
__global__ __launch_bounds__(256) void combine1(
    const float* __restrict__ po, const float* __restrict__ pm,
    const float* __restrict__ pl, float* __restrict__ z)
{
    __shared__ float coef[SPLITS][64];
    int tid = threadIdx.x;
    int h = blockIdx.x, b = blockIdx.y;

    if (tid < 64) {
        int q = tid;
        float mx = -1e30f;
        float ms[SPLITS];
#pragma unroll
        for (int s = 0; s < SPLITS; s++) {
            ms[s] = pm[((((long)s * BATCH + b) * NHEADS + h) * 64) + q];
            mx = fmaxf(mx, ms[s]);
        }
        float lsum = 0.0f;
        float es[SPLITS];
#pragma unroll
        for (int s = 0; s < SPLITS; s++) {
            es[s] = __expf(ms[s] - mx);
            lsum += es[s] * pl[((((long)s * BATCH + b) * NHEADS + h) * 64) + q];
        }
        float inv = 1.0f / lsum;
#pragma unroll
        for (int s = 0; s < SPLITS; s++) coef[s][q] = es[s] * inv;
    }
    __syncthreads();

#pragma unroll
    for (int i = 0; i < 16; i++) {
        int idx = tid + 256 * i;
        int q = idx >> 6, d = idx & 63;
        float sum = 0.0f;
#pragma unroll
        for (int s = 0; s < SPLITS; s++) {
            sum += coef[s][q] *
                   po[(((((long)s * BATCH + b) * NHEADS + h) * 64) + q) * 64 + d];
        }
        z[(long)b * NLAT * DLAT + (long)q * DLAT + h * DHEAD + d] = tf32f(sum);
    }
}

// ---------------------------------------------------------------------------
// Host launch
// ---------------------------------------------------------------------------
static void launch_gemm_mma(const float* A, const float* Bt, float* C,
                            int M, int N, int K)
{
    dim3 grid(N / GBN, (M + GBM - 1) / GBM);
    gemm_mma<<<grid, 128, GEMM_SMEM>>>(A, Bt, C, M, N, K);
}

extern "C" void kernel_launch(void* const* d_in, const int* in_sizes, int n_in,
                              void* d_out, int out_size)
{
    const float* x       = (const float*)d_in[0];
    const float* L       = (const float*)d_in[1];
    const float* W_q_lat = (const float*)d_in[2];
    const float* W_k_in  = (const float*)d_in[3];
    const float* W_v_in  = (const float*)d_in[4];
    const float* W_q_in  = (const float*)d_in[5];
    const float* W_k_lat = (const float*)d_in[6];
    const float* W_v_lat = (const float*)d_in[7];
    const float* W_out   = (const float*)d_in[8];
    float* out = (float*)d_out;

    float* scratch = nullptr;
    cudaGetSymbolAddress((void**)&scratch, g_scratch);

    float* gK    = scratch + OFF_K;
    float* gV    = scratch + OFF_V;
    float* gQx   = scratch + OFF_QX;
    float* gXlat = scratch + OFF_XLAT;
    float* gQ1   = scratch + OFF_Q1;
    float* gZ    = scratch + OFF_Z;
    float* gZ2   = scratch + OFF_Z2;
    float* gQl   = scratch + OFF_QL;
    float* gKl   = scratch + OFF_KL;
    float* gVl   = scratch + OFF_VL;
    float* gKz   = scratch + OFF_KZ;
    float* gVz   = scratch + OFF_VZ;
    float* gPo   = scratch + OFF_PO;
    float* gPm   = scratch + OFF_PM;
    float* gPl   = scratch + OFF_PL;
    float* gXtf  = scratch + OFF_XTF;
    float* gLtf  = scratch + OFF_LTF;

    float* tWkin  = scratch + OFF_WKINT;
    float* tWvin  = scratch + OFF_WVINT;
    float* tWqin  = scratch + OFF_WQINT;
    float* tWqlat = scratch + OFF_WQLATT;
    float* tWklat = scratch + OFF_WKLATT;
    float* tWvlat = scratch + OFF_WVLATT;
    float* tWout  = scratch + OFF_WOUTT;

    const int ATTN_SMEM = (4 * 64 * ALD + 192) * 4;   // 70400 B
    cudaFuncSetAttribute(attn64, cudaFuncAttributeMaxDynamicSharedMemorySize,
                         ATTN_SMEM);
    cudaFuncSetAttribute(attn1_split, cudaFuncAttributeMaxDynamicSharedMemorySize,
                         ATTN_SMEM);
    cudaFuncSetAttribute(gemm_mma, cudaFuncAttributeMaxDynamicSharedMemorySize,
                         GEMM_SMEM);

    // (1) transposes (tf32-rounded) + input rounding
    transp_all<<<dim3(64, 64, 7), dim3(32, 8)>>>(
        W_q_lat, W_k_in, W_v_in, W_q_in, W_k_lat, W_v_lat, W_out, scratch);
    {
        long n4x = (long)BT * DMODEL / 4;          // 8388608
        round_tf32<<<(unsigned)((n4x + 255) / 256), 256>>>(x, gXtf, n4x);
        long n4l = (long)NLAT * DLAT / 4;          // 16384
        round_tf32<<<(unsigned)((n4l + 255) / 256), 256>>>(L, gLtf, n4l);
    }

    // Big input projections (A operands pre-rounded)
    launch_gemm_mma(gLtf, tWqlat, gQ1, NLAT, DLAT, DLAT);
    launch_gemm_mma(gXtf, tWkin, gK, BT, DLAT, DMODEL);
    launch_gemm_mma(gXtf, tWvin, gV, BT, DLAT, DMODEL);
    launch_gemm_mma(gXtf, tWqin, gQx, BT, DLAT, DMODEL);

    // Stage 1: split-K attention + combine
    attn1_split<<<dim3(SPLITS, NHEADS, BATCH), 256, ATTN_SMEM>>>(
        gQ1, gK, gV, gPo, gPm, gPl);
    combine1<<<dim3(NHEADS, BATCH), 256>>>(gPo, gPm, gPl, gZ);

    // Stage 2 projections
    launch_gemm_mma(gZ, tWqlat, gQl, BATCH * NLAT, DLAT, DLAT);
    launch_gemm_mma(gZ, tWklat, gKl, BATCH * NLAT, DLAT, DLAT);
    launch_gemm_mma(gZ, tWvlat, gVl, BATCH * NLAT, DLAT, DLAT);

    // Stage 2: latent self-attention
    {
        dim3 grid(1, NHEADS, BATCH);
        attn64<<<grid, 256, ATTN_SMEM>>>(gQl, (long)NLAT * DLAT, gKl, gVl,
                                         (long)NLAT * DLAT, NLAT,
                                         gZ2, (long)NLAT * DLAT);
    }

    // Stage 3 projections
    launch_gemm_mma(gZ2, tWklat, gKz, BATCH * NLAT, DLAT, DLAT);
    launch_gemm_mma(gZ2, tWvlat, gVz, BATCH * NLAT, DLAT, DLAT);

    // Stage 3: tokens attend to latents
    {
        dim3 grid(TSEQ / 64, NHEADS, BATCH);
        attn64<<<grid, 256, ATTN_SMEM>>>(gQx, (long)TSEQ * DLAT, gKz, gVz,
                                         (long)NLAT * DLAT, NLAT,
                                         gXlat, (long)TSEQ * DLAT);
    }

    // Output projection
    launch_gemm_mma(gXlat, tWout, out, BT, DMODEL, DLAT);
}

// round 15
// speedup vs baseline: 4.0873x; 1.1797x over previous
#include <cuda_runtime.h>
#include <cuda_bf16.h>
#include <cstdint>

// Problem constants
#define BATCH 4
#define TSEQ 4096
#define DMODEL 2048
#define NLAT 64
#define DLAT 1024
#define NHEADS 16
#define DHEAD 64
#define BT (BATCH * TSEQ)        // 16384
#define SPLITS 16
#define KSPLIT 8                 // split-K factor for small GEMMs

// ---------------------------------------------------------------------------
// Scratch offsets (floats)
// ---------------------------------------------------------------------------
#define OFF_K      0L
#define OFF_V      16777216L
#define OFF_QX     33554432L
#define OFF_XLAT   50331648L
#define OFF_Q1     67108864L
#define OFF_Z      67174400L
#define OFF_Z2     67436544L
#define OFF_QL     67698688L
#define OFF_KL     67960832L
#define OFF_VL     68222976L
#define OFF_KZ     68485120L
#define OFF_VZ     68747264L
// transposed (tf32-rounded) weights [N,K]
#define OFF_WKINT  69009408L
#define OFF_WVINT  71106560L
#define OFF_WQINT  73203712L
#define OFF_WQLATT 75300864L
#define OFF_WKLATT 76349440L
#define OFF_WVLATT 77398016L
#define OFF_WOUTT  78446592L
// stage-1 split-K partials
#define OFF_PO     80543744L
#define OFF_PM     84738048L
#define OFF_PL     84803584L
// tf32-rounded inputs
#define OFF_XTF    84869120L
#define OFF_LTF    118423552L
#define SCRATCH_FLOATS 118489088L

__device__ float g_scratch[SCRATCH_FLOATS];

__device__ __forceinline__ uint32_t tf32r(float x) {
    uint32_t r;
    asm("cvt.rna.tf32.f32 %0, %1;" : "=r"(r) : "f"(x));
    return r;
}
__device__ __forceinline__ float tf32f(float x) {
    return __uint_as_float(tf32r(x));
}
__device__ __forceinline__ uint32_t smem_u32(const void* p) {
    uint32_t a;
    asm("{ .reg .u64 t; cvta.to.shared.u64 t, %1; cvt.u32.u64 %0, t; }"
        : "=r"(a) : "l"(p));
    return a;
}

// ---------------------------------------------------------------------------
// Utility kernels
// ---------------------------------------------------------------------------
__global__ void round_tf32(const float* __restrict__ src, float* __restrict__ dst,
                           long n4)
{
    long i = (long)blockIdx.x * blockDim.x + threadIdx.x;
    if (i < n4) {
        float4 v = ((const float4*)src)[i];
        v.x = tf32f(v.x); v.y = tf32f(v.y); v.z = tf32f(v.z); v.w = tf32f(v.w);
        ((float4*)dst)[i] = v;
    }
}

__global__ void zero_buf(float* __restrict__ dst, long n4)
{
    long i = (long)blockIdx.x * blockDim.x + threadIdx.x;
    if (i < n4) ((float4*)dst)[i] = make_float4(0.f, 0.f, 0.f, 0.f);
}

// ---------------------------------------------------------------------------
// tf32 mma.sync GEMM, cp.async 3-stage pipeline, BK=32, ONE sync per chunk.
// C[M,N] = A[M,K] * Bt[N,K]^T (operands pre-rounded to tf32 values).
// CTA tile 128x128, 128 threads (2x2 warps), warp tile 64x64.
// ATOMIC=true: accumulate into C with atomicAdd (split-K, C pre-zeroed);
//              blockIdx.z selects K-slice of length klen.
// ---------------------------------------------------------------------------
#define GBM 128
#define GBN 128
#define GBK 32
#define LDSA 36
#define BUF_FLOATS (GBM * LDSA)                 // 4608 floats per array
#define STAGE_BYTES (2 * BUF_FLOATS * 4)        // 36864 (A + B)
#define GSTAGES 3
#define GEMM_SMEM (GSTAGES * STAGE_BYTES)       // 110592

template <bool ATOMIC>
__global__ __launch_bounds__(128, 2) void gemm_mma(
    const float* __restrict__ A, const float* __restrict__ Bt,
    float* __restrict__ C, int M, int N, int K, int klen)
{
    extern __shared__ float sm[];
    const uint32_t smb = smem_u32(sm);
    const int tid = threadIdx.x;
    const int wid = tid >> 5, lane = tid & 31;
    const int grp = lane >> 2, qc = lane & 3;
    const int warp_m = wid & 1, warp_n = wid >> 1;
    const int row0 = blockIdx.y * GBM;
    const int col0 = blockIdx.x * GBN;
    const int kofs = ATOMIC ? blockIdx.z * klen : 0;
    const int nchunks = klen / GBK;

    // Per-thread cp.async mapping: 8 A rows + 8 B rows, 16B each.
    // chunk = 128 rows x 32 floats = 1024 float4; f4 = tid + 128*i.
    const float* asrc[8];
    const float* bsrc[8];
    uint32_t adst[8], bdst[8];
    int asz[8];
#pragma unroll
    for (int i = 0; i < 8; i++) {
        int f4 = tid + 128 * i;
        int r = f4 >> 3, cc = (f4 & 7) * 4;
        asrc[i] = A + (long)(row0 + r) * K + kofs + cc;
        bsrc[i] = Bt + (long)(col0 + r) * K + kofs + cc;
        adst[i] = smb + (uint32_t)(r * LDSA + cc) * 4;
        bdst[i] = smb + (uint32_t)(BUF_FLOATS + r * LDSA + cc) * 4;
        asz[i] = (row0 + r < M) ? 16 : 0;
    }

#define GISSUE(c, s) do { \
    uint32_t _so = (uint32_t)(s) * STAGE_BYTES; \
    long _go = (long)(c) * GBK; \
    _Pragma("unroll") \
    for (int _i = 0; _i < 8; _i++) { \
        asm volatile("cp.async.cg.shared.global [%0], [%1], 16, %2;" \
            :: "r"(adst[_i] + _so), "l"(asrc[_i] + _go), "r"(asz[_i])); \
        asm volatile("cp.async.cg.shared.global [%0], [%1], 16;" \
            :: "r"(bdst[_i] + _so), "l"(bsrc[_i] + _go)); \
    } \
    asm volatile("cp.async.commit_group;"); \
} while (0)

    float acc[4][8][4];
#pragma unroll
    for (int i = 0; i < 4; i++)
#pragma unroll
        for (int j = 0; j < 8; j++)
#pragma unroll
            for (int l = 0; l < 4; l++) acc[i][j][l] = 0.0f;

    GISSUE(0, 0);
    GISSUE(1, 1);

    for (int c = 0; c < nchunks; c++) {
        if (c + 1 < nchunks)
            asm volatile("cp.async.wait_group 1;");
        else
            asm volatile("cp.async.wait_group 0;");
        __syncthreads();   // all warps done with chunk c-1; stage c ready

        int cn = c + GSTAGES - 1;
        if (cn < nchunks) GISSUE(cn, cn % GSTAGES);

        float* As = sm + (c % GSTAGES) * (2 * BUF_FLOATS);
        float* Bs = As + BUF_FLOATS;

#pragma unroll
        for (int ks = 0; ks < 4; ks++) {
            int k0 = ks * 8;
            uint32_t a[4][4], b[8][2];
#pragma unroll
            for (int mt = 0; mt < 4; mt++) {
                int r = warp_m * 64 + mt * 16 + grp;
                const uint32_t* p0 = (const uint32_t*)(As + r * LDSA + k0 + qc);
                const uint32_t* p1 = (const uint32_t*)(As + (r + 8) * LDSA + k0 + qc);
                a[mt][0] = p0[0]; a[mt][2] = p0[4];
                a[mt][1] = p1[0]; a[mt][3] = p1[4];
            }
#pragma unroll
            for (int nt = 0; nt < 8; nt++) {
                int r = warp_n * 64 + nt * 8 + grp;
                const uint32_t* p = (const uint32_t*)(Bs + r * LDSA + k0 + qc);
                b[nt][0] = p[0]; b[nt][1] = p[4];
            }
#pragma unroll
            for (int mt = 0; mt < 4; mt++)
#pragma unroll
                for (int nt = 0; nt < 8; nt++)
                    asm volatile(
                        "mma.sync.aligned.m16n8k8.row.col.f32.tf32.tf32.f32 "
                        "{%0,%1,%2,%3}, {%4,%5,%6,%7}, {%8,%9}, {%0,%1,%2,%3};"
                        : "+f"(acc[mt][nt][0]), "+f"(acc[mt][nt][1]),
                          "+f"(acc[mt][nt][2]), "+f"(acc[mt][nt][3])
                        : "r"(a[mt][0]), "r"(a[mt][1]), "r"(a[mt][2]), "r"(a[mt][3]),
                          "r"(b[nt][0]), "r"(b[nt][1]));
        }
        // no trailing sync: with 3 stages, chunk c+2 writes stage (c+2)%3
        // which no warp still reads; leading barrier orders compute-done.
    }

    // Epilogue
#pragma unroll
    for (int mt = 0; mt < 4; mt++) {
        int r = row0 + warp_m * 64 + mt * 16 + grp;
#pragma unroll
        for (int nt = 0; nt < 8; nt++) {
            int col = col0 + warp_n * 64 + nt * 8 + qc * 2;
            if (ATOMIC) {
                if (r < M) {
                    atomicAdd(C + (long)r * N + col, acc[mt][nt][0]);
                    atomicAdd(C + (long)r * N + col + 1, acc[mt][nt][1]);
                }
                if (r + 8 < M) {
                    atomicAdd(C + (long)(r + 8) * N + col, acc[mt][nt][2]);
                    atomicAdd(C + (long)(r + 8) * N + col + 1, acc[mt][nt][3]);
                }
            } else {
                if (r < M)
                    *(float2*)(C + (long)r * N + col) =
                        make_float2(acc[mt][nt][0], acc[mt][nt][1]);
                if (r + 8 < M)
                    *(float2*)(C + (long)(r + 8) * N + col) =
                        make_float2(acc[mt][nt][2], acc[mt][nt][3]);
            }
        }
    }
#undef GISSUE
}

// ---------------------------------------------------------------------------
// Batched transpose of all 7 weights, tf32-rounded at store.
// ---------------------------------------------------------------------------
__global__ void transp_all(
    const float* __restrict__ W_q_lat, const float* __restrict__ W_k_in,
    const float* __restrict__ W_v_in,  const float* __restrict__ W_q_in,
    const float* __restrict__ W_k_lat, const float* __restrict__ W_v_lat,
    const float* __restrict__ W_out,   float* __restrict__ scr)
{
    const float* S; float* D; int R, C;
    switch (blockIdx.z) {
        case 0: S = W_k_in;  D = scr + OFF_WKINT;  R = DMODEL; C = DLAT;   break;
        case 1: S = W_v_in;  D = scr + OFF_WVINT;  R = DMODEL; C = DLAT;   break;
        case 2: S = W_q_in;  D = scr + OFF_WQINT;  R = DMODEL; C = DLAT;   break;
        case 3: S = W_q_lat; D = scr + OFF_WQLATT; R = DLAT;   C = DLAT;   break;
        case 4: S = W_k_lat; D = scr + OFF_WKLATT; R = DLAT;   C = DLAT;   break;
        case 5: S = W_v_lat; D = scr + OFF_WVLATT; R = DLAT;   C = DLAT;   break;
        default: S = W_out;  D = scr + OFF_WOUTT;  R = DLAT;   C = DMODEL; break;
    }
    int bx = blockIdx.x * 32, by = blockIdx.y * 32;
    if (bx >= C || by >= R) return;
    __shared__ float t[32][33];
    int x = threadIdx.x, y = threadIdx.y;
#pragma unroll
    for (int j = 0; j < 32; j += 8)
        t[y + j][x] = S[(long)(by + y + j) * C + bx + x];
    __syncthreads();
#pragma unroll
    for (int j = 0; j < 32; j += 8)
        D[(long)(bx + y + j) * R + by + x] = tf32f(t[x][y + j]);
}

// ---------------------------------------------------------------------------
// Flash attention for d_h = 64 (stages 2 and 3); output tf32-rounded.
// ---------------------------------------------------------------------------
#define ALD 68

__global__ __launch_bounds__(256) void attn64(
    const float* __restrict__ Q, long qBatch,
    const float* __restrict__ Kp, const float* __restrict__ Vp, long kvBatch,
    int nkeys, float* __restrict__ Out, long oBatch)
{
    extern __shared__ float smf[];
    float* Qs = smf;
    float* Ks = Qs + 64 * ALD;
    float* Vs = Ks + 64 * ALD;
    float* Ps = Vs + 64 * ALD;
    float* mrow = Ps + 64 * ALD;
    float* lrow = mrow + 64;
    float* crow = lrow + 64;

    int tid = threadIdx.x;
    int h = blockIdx.y, b = blockIdx.z;
    int qtile = blockIdx.x;
    const float scale = 0.125f;

    const float* Qbase = Q + (long)b * qBatch + (long)qtile * 64 * DLAT + h * DHEAD;
    const float* Kbase = Kp + (long)b * kvBatch + h * DHEAD;
    const float* Vbase = Vp + (long)b * kvBatch + h * DHEAD;

#pragma unroll
    for (int i = 0; i < 16; i++) {
        int idx = tid + 256 * i;
        int q = idx >> 6, d = idx & 63;
        Qs[d * ALD + q] = Qbase[(long)q * DLAT + d] * scale;
    }
    if (tid < 64) { mrow[tid] = -1e30f; lrow[tid] = 0.0f; }
    __syncthreads();

    int tx = tid & 15, ty = tid >> 4;
    float o[4][4];
#pragma unroll
    for (int i = 0; i < 4; i++)
#pragma unroll
        for (int j = 0; j < 4; j++) o[i][j] = 0.0f;

    for (int k0 = 0; k0 < nkeys; k0 += 64) {
#pragma unroll
        for (int i = 0; i < 16; i++) {
            int idx = tid + 256 * i;
            int k = idx >> 6, d = idx & 63;
            float kv = Kbase[(long)(k0 + k) * DLAT + d];
            float vv = Vbase[(long)(k0 + k) * DLAT + d];
            Ks[d * ALD + k] = kv;
            Vs[k * ALD + d] = vv;
        }
        __syncthreads();

        float s[4][4];
#pragma unroll
        for (int i = 0; i < 4; i++)
#pragma unroll
            for (int j = 0; j < 4; j++) s[i][j] = 0.0f;
#pragma unroll
        for (int d = 0; d < 64; d++) {
            float4 qf = *(float4*)&Qs[d * ALD + ty * 4];
            float4 kf = *(float4*)&Ks[d * ALD + tx * 4];
            float qa[4] = {qf.x, qf.y, qf.z, qf.w};
            float ka[4] = {kf.x, kf.y, kf.z, kf.w};
#pragma unroll
            for (int ki = 0; ki < 4; ki++)
#pragma unroll
                for (int qj = 0; qj < 4; qj++)
                    s[ki][qj] += ka[ki] * qa[qj];
        }
#pragma unroll
        for (int ki = 0; ki < 4; ki++)
            *(float4*)&Ps[(tx * 4 + ki) * ALD + ty * 4] =
                make_float4(s[ki][0], s[ki][1], s[ki][2], s[ki][3]);
        __syncthreads();

        if (tid < 64) {
            int q = tid;
            float mold = mrow[q];
            float mx = mold;
            for (int k = 0; k < 64; k++) mx = fmaxf(mx, Ps[k * ALD + q]);
            float c = __expf(mold - mx);
            float l = lrow[q] * c;
            for (int k = 0; k < 64; k++) {
                float p = __expf(Ps[k * ALD + q] - mx);
                Ps[k * ALD + q] = p;
                l += p;
            }
            mrow[q] = mx; lrow[q] = l; crow[q] = c;
        }
        __syncthreads();

        float cq[4];
        *(float4*)cq = *(float4*)&crow[ty * 4];
#pragma unroll
        for (int i = 0; i < 4; i++)
#pragma unroll
            for (int j = 0; j < 4; j++) o[i][j] *= cq[i];

#pragma unroll 8
        for (int j = 0; j < 64; j++) {
            float4 pf = *(float4*)&Ps[j * ALD + ty * 4];
            float4 vf = *(float4*)&Vs[j * ALD + tx * 4];
            float pa[4] = {pf.x, pf.y, pf.z, pf.w};
            float va[4] = {vf.x, vf.y, vf.z, vf.w};
#pragma unroll
            for (int qi = 0; qi < 4; qi++)
#pragma unroll
                for (int dj = 0; dj < 4; dj++)
                    o[qi][dj] += pa[qi] * va[dj];
        }
        __syncthreads();
    }

    float lq[4];
    *(float4*)lq = *(float4*)&lrow[ty * 4];
    float* Obase = Out + (long)b * oBatch + (long)qtile * 64 * DLAT + h * DHEAD;
#pragma unroll
    for (int qi = 0; qi < 4; qi++) {
        float inv = 1.0f / lq[qi];
        int q = ty * 4 + qi;
        float* op = Obase + (long)q * DLAT + tx * 4;
        *(float4*)op = make_float4(tf32f(o[qi][0] * inv), tf32f(o[qi][1] * inv),
                                   tf32f(o[qi][2] * inv), tf32f(o[qi][3] * inv));
    }
}

// ---------------------------------------------------------------------------
// Stage-1 split-K attention: grid (SPLITS, NHEADS, BATCH).
// ---------------------------------------------------------------------------
__global__ __launch_bounds__(256) void attn1_split(
    const float* __restrict__ Q,
    const float* __restrict__ Kp, const float* __restrict__ Vp,
    float* __restrict__ po, float* __restrict__ pm, float* __restrict__ pl)
{
    extern __shared__ float smf[];
    float* Qs = smf;
    float* Ks = Qs + 64 * ALD;
    float* Vs = Ks + 64 * ALD;
    float* Ps = Vs + 64 * ALD;
    float* mrow = Ps + 64 * ALD;
    float* lrow = mrow + 64;
    float* crow = lrow + 64;

    int tid = threadIdx.x;
    int s = blockIdx.x, h = blockIdx.y, b = blockIdx.z;
    const float scale = 0.125f;

    const float* Qbase = Q + h * DHEAD;
    const float* Kbase = Kp + (long)b * TSEQ * DLAT + h * DHEAD;
    const float* Vbase = Vp + (long)b * TSEQ * DLAT + h * DHEAD;
    const int key0 = s * (TSEQ / SPLITS);

#pragma unroll
    for (int i = 0; i < 16; i++) {
        int idx = tid + 256 * i;
        int q = idx >> 6, d = idx & 63;
        Qs[d * ALD + q] = Qbase[(long)q * DLAT + d] * scale;
    }
    if (tid < 64) { mrow[tid] = -1e30f; lrow[tid] = 0.0f; }
    __syncthreads();

    int tx = tid & 15, ty = tid >> 4;
    float o[4][4];
#pragma unroll
    for (int i = 0; i < 4; i++)
#pragma unroll
        for (int j = 0; j < 4; j++) o[i][j] = 0.0f;

    for (int kc = 0; kc < TSEQ / SPLITS; kc += 64) {
        int k0 = key0 + kc;
#pragma unroll
        for (int i = 0; i < 16; i++) {
            int idx = tid + 256 * i;
            int k = idx >> 6, d = idx & 63;
            Ks[d * ALD + k] = Kbase[(long)(k0 + k) * DLAT + d];
            Vs[k * ALD + d] = Vbase[(long)(k0 + k) * DLAT + d];
        }
        __syncthreads();

        float sacc[4][4];
#pragma unroll
        for (int i = 0; i < 4; i++)
#pragma unroll
            for (int j = 0; j < 4; j++) sacc[i][j] = 0.0f;
#pragma unroll
        for (int d = 0; d < 64; d++) {
            float4 qf = *(float4*)&Qs[d * ALD + ty * 4];
            float4 kf = *(float4*)&Ks[d * ALD + tx * 4];
            float qa[4] = {qf.x, qf.y, qf.z, qf.w};
            float ka[4] = {kf.x, kf.y, kf.z, kf.w};
#pragma unroll
            for (int ki = 0; ki < 4; ki++)
#pragma unroll
                for (int qj = 0; qj < 4; qj++)
                    sacc[ki][qj] += ka[ki] * qa[qj];
        }
#pragma unroll
        for (int ki = 0; ki < 4; ki++)
            *(float4*)&Ps[(tx * 4 + ki) * ALD + ty * 4] =
                make_float4(sacc[ki][0], sacc[ki][1], sacc[ki][2], sacc[ki][3]);
        __syncthreads();

        if (tid < 64) {
            int q = tid;
            float mold = mrow[q];
            float mx = mold;
            for (int k = 0; k < 64; k++) mx = fmaxf(mx, Ps[k * ALD + q]);
            float c = __expf(mold - mx);
            float l = lrow[q] * c;
            for (int k = 0; k < 64; k++) {
                float p = __expf(Ps[k * ALD + q] - mx);
                Ps[k * ALD + q] = p;
                l += p;
            }
            mrow[q] = mx; lrow[q] = l; crow[q] = c;
        }
        __syncthreads();

        float cq[4];
        *(float4*)cq = *(float4*)&crow[ty * 4];
#pragma unroll
        for (int i = 0; i < 4; i++)
#pragma unroll
            for (int j = 0; j < 4; j++) o[i][j] *= cq[i];

#pragma unroll 8
        for (int j = 0; j < 64; j++) {
            float4 pf = *(float4*)&Ps[j * ALD + ty * 4];
            float4 vf = *(float4*)&Vs[j * ALD + tx * 4];
            float pa[4] = {pf.x, pf.y, pf.z, pf.w};
            float va[4] = {vf.x, vf.y, vf.z, vf.w};
#pragma unroll
            for (int qi = 0; qi < 4; qi++)
#pragma unroll
                for (int dj = 0; dj < 4; dj++)
                    o[qi][dj] += pa[qi] * va[dj];
        }
        __syncthreads();
    }

    long base = ((((long)s * BATCH + b) * NHEADS + h) * 64);
    float* pob = po + base * 64;
#pragma unroll
    for (int qi = 0; qi < 4; qi++) {
        int q = ty * 4 + qi;
        *(float4*)(pob + (long)q * 64 + tx * 4) =
            make_float4(o[qi][0], o[qi][1], o[qi][2], o[qi][3]);
    }
    if (tid < 64) {
        pm[base + tid] = mrow[tid];
        pl[base + tid] = lrow[tid];
    }
}

// ---------------------------------------------------------------------------
// Combine stage-1 partials -> z (tf32-rounded).
// ---------------------------------------------------------------------------
__global__ __launch_bounds__(256) void combine1(
    const float* __restrict__ po, const float* __restrict__ pm,
    const float* __restrict__ pl, float* __restrict__ z)
{
    __shared__ float coef[SPLITS][64];
    int tid = threadIdx.x;
    int h = blockIdx.x, b = blockIdx.y;

    if (tid < 64) {
        int q = tid;
        float mx = -1e30f;
        float ms[SPLITS];
#pragma unroll
        for (int s = 0; s < SPLITS; s++) {
            ms[s] = pm[((((long)s * BATCH + b) * NHEADS + h) * 64) + q];
            mx = fmaxf(mx, ms[s]);
        }
        float lsum = 0.0f;
        float es[SPLITS];
#pragma unroll
        for (int s = 0; s < SPLITS; s++) {
            es[s] = __expf(ms[s] - mx);
            lsum += es[s] * pl[((((long)s * BATCH + b) * NHEADS + h) * 64) + q];
        }
        float inv = 1.0f / lsum;
#pragma unroll
        for (int s = 0; s < SPLITS; s++) coef[s][q] = es[s] * inv;
    }
    __syncthreads();

#pragma unroll
    for (int i = 0; i < 16; i++) {
        int idx = tid + 256 * i;
        int q = idx >> 6, d = idx & 63;
        float sum = 0.0f;
#pragma unroll
        for (int s = 0; s < SPLITS; s++) {
            sum += coef[s][q] *
                   po[(((((long)s * BATCH + b) * NHEADS + h) * 64) + q) * 64 + d];
        }
        z[(long)b * NLAT * DLAT + (long)q * DLAT + h * DHEAD + d] = tf32f(sum);
    }
}

// ---------------------------------------------------------------------------
// Host launch
// ---------------------------------------------------------------------------
static void launch_gemm_big(const float* A, const float* Bt, float* C,
                            int M, int N, int K)
{
    dim3 grid(N / GBN, (M + GBM - 1) / GBM);
    gemm_mma<false><<<grid, 128, GEMM_SMEM>>>(A, Bt, C, M, N, K, K);
}

static void launch_gemm_small(const float* A, const float* Bt, float* C,
                              int M, int N, int K)
{
    dim3 grid(N / GBN, (M + GBM - 1) / GBM, KSPLIT);
    gemm_mma<true><<<grid, 128, GEMM_SMEM>>>(A, Bt, C, M, N, K, K / KSPLIT);
}

extern "C" void kernel_launch(void* const* d_in, const int* in_sizes, int n_in,
                              void* d_out, int out_size)
{
    const float* x       = (const float*)d_in[0];
    const float* L       = (const float*)d_in[1];
    const float* W_q_lat = (const float*)d_in[2];
    const float* W_k_in  = (const float*)d_in[3];
    const float* W_v_in  = (const float*)d_in[4];
    const float* W_q_in  = (const float*)d_in[5];
    const float* W_k_lat = (const float*)d_in[6];
    const float* W_v_lat = (const float*)d_in[7];
    const float* W_out   = (const float*)d_in[8];
    float* out = (float*)d_out;

    float* scratch = nullptr;
    cudaGetSymbolAddress((void**)&scratch, g_scratch);

    float* gK    = scratch + OFF_K;
    float* gV    = scratch + OFF_V;
    float* gQx   = scratch + OFF_QX;
    float* gXlat = scratch + OFF_XLAT;
    float* gQ1   = scratch + OFF_Q1;
    float* gZ    = scratch + OFF_Z;
    float* gZ2   = scratch + OFF_Z2;
    float* gQl   = scratch + OFF_QL;
    float* gKl   = scratch + OFF_KL;
    float* gVl   = scratch + OFF_VL;
    float* gKz   = scratch + OFF_KZ;
    float* gVz   = scratch + OFF_VZ;
    float* gPo   = scratch + OFF_PO;
    float* gPm   = scratch + OFF_PM;
    float* gPl   = scratch + OFF_PL;
    float* gXtf  = scratch + OFF_XTF;
    float* gLtf  = scratch + OFF_LTF;

    float* tWkin  = scratch + OFF_WKINT;
    float* tWvin  = scratch + OFF_WVINT;
    float* tWqin  = scratch + OFF_WQINT;
    float* tWqlat = scratch + OFF_WQLATT;
    float* tWklat = scratch + OFF_WKLATT;
    float* tWvlat = scratch + OFF_WVLATT;
    float* tWout  = scratch + OFF_WOUTT;

    const int ATTN_SMEM = (4 * 64 * ALD + 192) * 4;   // 70400 B
    cudaFuncSetAttribute(attn64, cudaFuncAttributeMaxDynamicSharedMemorySize,
                         ATTN_SMEM);
    cudaFuncSetAttribute(attn1_split, cudaFuncAttributeMaxDynamicSharedMemorySize,
                         ATTN_SMEM);
    cudaFuncSetAttribute(gemm_mma<false>,
                         cudaFuncAttributeMaxDynamicSharedMemorySize, GEMM_SMEM);
    cudaFuncSetAttribute(gemm_mma<true>,
                         cudaFuncAttributeMaxDynamicSharedMemorySize, GEMM_SMEM);

    // (1) transp  (2) zero q1  (3) zero gQl..gVz  (4) round x  (5) round L
    transp_all<<<dim3(64, 64, 7), dim3(32, 8)>>>(
        W_q_lat, W_k_in, W_v_in, W_q_in, W_k_lat, W_v_lat, W_out, scratch);
    zero_buf<<<(NLAT * DLAT / 4 + 255) / 256, 256>>>(gQ1, NLAT * DLAT / 4);
    zero_buf<<<(5 * BATCH * NLAT * DLAT / 4 + 255) / 256, 256>>>(
        gQl, 5L * BATCH * NLAT * DLAT / 4);
    {
        long n4x = (long)BT * DMODEL / 4;
        round_tf32<<<(unsigned)((n4x + 255) / 256), 256>>>(x, gXtf, n4x);
        long n4l = (long)NLAT * DLAT / 4;
        round_tf32<<<(unsigned)((n4l + 255) / 256), 256>>>(L, gLtf, n4l);
    }

    // (6) big GEMM — profiled launch
    launch_gemm_big(gXtf, tWkin, gK, BT, DLAT, DMODEL);
    launch_gemm_big(gXtf, tWvin, gV, BT, DLAT, DMODEL);
    launch_gemm_big(gXtf, tWqin, gQx, BT, DLAT, DMODEL);
    launch_gemm_small(gLtf, tWqlat, gQ1, NLAT, DLAT, DLAT);

    // Stage 1: split-K attention + combine
    attn1_split<<<dim3(SPLITS, NHEADS, BATCH), 256, ATTN_SMEM>>>(
        gQ1, gK, gV, gPo, gPm, gPl);
    combine1<<<dim3(NHEADS, BATCH), 256>>>(gPo, gPm, gPl, gZ);

    // Stage 2 projections (split-K small GEMMs)
    launch_gemm_small(gZ, tWqlat, gQl, BATCH * NLAT, DLAT, DLAT);
    launch_gemm_small(gZ, tWklat, gKl, BATCH * NLAT, DLAT, DLAT);
    launch_gemm_small(gZ, tWvlat, gVl, BATCH * NLAT, DLAT, DLAT);

    // Stage 2: latent self-attention
    {
        dim3 grid(1, NHEADS, BATCH);
        attn64<<<grid, 256, ATTN_SMEM>>>(gQl, (long)NLAT * DLAT, gKl, gVl,
                                         (long)NLAT * DLAT, NLAT,
                                         gZ2, (long)NLAT * DLAT);
    }

    // Stage 3 projections
    launch_gemm_small(gZ2, tWklat, gKz, BATCH * NLAT, DLAT, DLAT);
    launch_gemm_small(gZ2, tWvlat, gVz, BATCH * NLAT, DLAT, DLAT);

    // Stage 3: tokens attend to latents
    {
        dim3 grid(TSEQ / 64, NHEADS, BATCH);
        attn64<<<grid, 256, ATTN_SMEM>>>(gQx, (long)TSEQ * DLAT, gKz, gVz,
                                         (long)NLAT * DLAT, NLAT,
                                         gXlat, (long)TSEQ * DLAT);
    }

    // Output projection
    launch_gemm_big(gXlat, tWout, out, BT, DMODEL, DLAT);
}